// round 1
// baseline (speedup 1.0000x reference)
#include <cuda_runtime.h>
#include <cuda_bf16.h>
#include <math.h>

// Problem constants
#define BB     2
#define CC     512
#define HEADS  8
#define DPH    16
#define TOT    128          // HEADS*DPH
#define NN     2304         // 48*48
#define M_QKV  384          // 3*TOT
#define K_QKV  512
#define M_PRJ  512
#define K_PRJ  128

// Scratch (device globals — no allocation allowed)
__device__ float g_q [BB*HEADS*NN*DPH];   // [b][h][n][d]
__device__ float g_k [BB*HEADS*NN*DPH];
__device__ float g_v [BB*HEADS*NN*DPH];
__device__ float g_ao[BB*TOT*NN];         // [b][t][n], t = h*16+d

// ---------------------------------------------------------------------------
// K1: qkv = w_qkv[384,512] @ x[b,512,2304]; scatter into q/k/v [b,h,n,d]
// 64x64 tile, 16 k-step, 256 threads, 4x4 micro-tile.
// ---------------------------------------------------------------------------
__global__ void __launch_bounds__(256) qkv_gemm(const float* __restrict__ x,
                                                const float* __restrict__ w) {
    __shared__ float As[16][64];
    __shared__ float Bs[16][64];
    const int b     = blockIdx.z;
    const int oBase = blockIdx.y * 64;
    const int nBase = blockIdx.x * 64;
    const int tid   = threadIdx.x;
    const int tx    = tid & 15;
    const int ty    = tid >> 4;
    const float* xb = x + (size_t)b * CC * NN;

    float acc[4][4] = {};
    for (int k0 = 0; k0 < K_QKV; k0 += 16) {
        {   // A tile: 64 rows(o) x 16 cols(k), stored transposed
            int i = tid * 4;
            int r = i >> 4, c = i & 15;
            float4 v = *(const float4*)&w[(oBase + r) * K_QKV + k0 + c];
            As[c+0][r] = v.x; As[c+1][r] = v.y; As[c+2][r] = v.z; As[c+3][r] = v.w;
        }
        {   // B tile: 16 rows(k) x 64 cols(n)
            int i = tid * 4;
            int r = i >> 6, c = i & 63;
            *(float4*)&Bs[r][c] = *(const float4*)&xb[(k0 + r) * NN + nBase + c];
        }
        __syncthreads();
        #pragma unroll
        for (int kk = 0; kk < 16; kk++) {
            float a0 = As[kk][ty*4+0], a1 = As[kk][ty*4+1];
            float a2 = As[kk][ty*4+2], a3 = As[kk][ty*4+3];
            float b0 = Bs[kk][tx*4+0], b1 = Bs[kk][tx*4+1];
            float b2 = Bs[kk][tx*4+2], b3 = Bs[kk][tx*4+3];
            acc[0][0] = fmaf(a0,b0,acc[0][0]); acc[0][1] = fmaf(a0,b1,acc[0][1]);
            acc[0][2] = fmaf(a0,b2,acc[0][2]); acc[0][3] = fmaf(a0,b3,acc[0][3]);
            acc[1][0] = fmaf(a1,b0,acc[1][0]); acc[1][1] = fmaf(a1,b1,acc[1][1]);
            acc[1][2] = fmaf(a1,b2,acc[1][2]); acc[1][3] = fmaf(a1,b3,acc[1][3]);
            acc[2][0] = fmaf(a2,b0,acc[2][0]); acc[2][1] = fmaf(a2,b1,acc[2][1]);
            acc[2][2] = fmaf(a2,b2,acc[2][2]); acc[2][3] = fmaf(a2,b3,acc[2][3]);
            acc[3][0] = fmaf(a3,b0,acc[3][0]); acc[3][1] = fmaf(a3,b1,acc[3][1]);
            acc[3][2] = fmaf(a3,b2,acc[3][2]); acc[3][3] = fmaf(a3,b3,acc[3][3]);
        }
        __syncthreads();
    }
    #pragma unroll
    for (int i = 0; i < 4; i++) {
        int o    = oBase + ty*4 + i;
        int part = o >> 7;          // 0=q,1=k,2=v
        int t    = o & 127;
        int h    = t >> 4, d = t & 15;
        #pragma unroll
        for (int j = 0; j < 4; j++) {
            int n = nBase + tx*4 + j;
            int idx = ((b*HEADS + h)*NN + n)*DPH + d;
            float val = acc[i][j];
            if      (part == 0) g_q[idx] = val;
            else if (part == 1) g_k[idx] = val;
            else                g_v[idx] = val;
        }
    }
}

// ---------------------------------------------------------------------------
// K2: L2-normalize q and k rows (over dph=16), in place.
// ---------------------------------------------------------------------------
__global__ void __launch_bounds__(256) norm_qk() {
    int i = blockIdx.x * 256 + threadIdx.x;
    if (i >= BB*HEADS*NN) return;
    {
        float* p = g_q + (size_t)i * DPH;
        float s = 0.f;
        #pragma unroll
        for (int d = 0; d < DPH; d++) s = fmaf(p[d], p[d], s);
        float inv = 1.0f / fmaxf(sqrtf(s), 1e-12f);
        #pragma unroll
        for (int d = 0; d < DPH; d++) p[d] *= inv;
    }
    {
        float* p = g_k + (size_t)i * DPH;
        float s = 0.f;
        #pragma unroll
        for (int d = 0; d < DPH; d++) s = fmaf(p[d], p[d], s);
        float inv = 1.0f / fmaxf(sqrtf(s), 1e-12f);
        #pragma unroll
        for (int d = 0; d < DPH; d++) p[d] *= inv;
    }
}

// ---------------------------------------------------------------------------
// K3: flash-style attention. One thread = one query row (online softmax).
// K/V tiles of 128 rows staged in SMEM (broadcast reads).
// ---------------------------------------------------------------------------
__global__ void __launch_bounds__(256) attn_kernel(const float* __restrict__ temperature) {
    __shared__ float Ks[128*16];
    __shared__ float Vs[128*16];
    const int b   = blockIdx.z;
    const int h   = blockIdx.y;
    const int tid = threadIdx.x;
    const int n   = blockIdx.x * 256 + tid;
    const float temp = temperature[h];
    const int base = (b*HEADS + h) * NN * DPH;

    float q[16];
    #pragma unroll
    for (int d = 0; d < 16; d++) q[d] = g_q[base + n*DPH + d] * temp;  // fold temperature

    float m = -1e30f, l = 0.f;
    float acc[16] = {};

    for (int t0 = 0; t0 < NN; t0 += 128) {
        __syncthreads();
        const float* kg = g_k + base + t0*DPH;
        const float* vg = g_v + base + t0*DPH;
        #pragma unroll
        for (int i = 0; i < 2; i++) {
            *(float4*)&Ks[tid*4 + i*1024] = *(const float4*)&kg[tid*4 + i*1024];
            *(float4*)&Vs[tid*4 + i*1024] = *(const float4*)&vg[tid*4 + i*1024];
        }
        __syncthreads();
        for (int j = 0; j < 128; j++) {
            const float* kr = &Ks[j*16];
            float s = 0.f;
            #pragma unroll
            for (int d = 0; d < 16; d++) s = fmaf(q[d], kr[d], s);
            const float* vr = &Vs[j*16];
            if (s <= m) {                      // common path: no max update
                float p = __expf(s - m);
                l += p;
                #pragma unroll
                for (int d = 0; d < 16; d++) acc[d] = fmaf(p, vr[d], acc[d]);
            } else {                           // rare: rescale state
                float corr = __expf(m - s);
                l = fmaf(l, corr, 1.0f);
                #pragma unroll
                for (int d = 0; d < 16; d++) acc[d] = fmaf(acc[d], corr, vr[d]);
                m = s;
            }
        }
    }
    const float inv = 1.0f / l;
    #pragma unroll
    for (int d = 0; d < 16; d++)
        g_ao[(b*TOT + h*DPH + d) * NN + n] = acc[d] * inv;
}

// ---------------------------------------------------------------------------
// K4: projection  y[b,c,n] = w_out[c,t] @ ao[b,t,n]   (M=512, K=128, N=2304)
// ---------------------------------------------------------------------------
__global__ void __launch_bounds__(256) proj_gemm(const float* __restrict__ w,
                                                 float* __restrict__ out) {
    __shared__ float As[16][64];
    __shared__ float Bs[16][64];
    const int b     = blockIdx.z;
    const int oBase = blockIdx.y * 64;
    const int nBase = blockIdx.x * 64;
    const int tid   = threadIdx.x;
    const int tx    = tid & 15;
    const int ty    = tid >> 4;
    const float* ao = g_ao + (size_t)b * TOT * NN;

    float acc[4][4] = {};
    for (int k0 = 0; k0 < K_PRJ; k0 += 16) {
        {
            int i = tid * 4;
            int r = i >> 4, c = i & 15;
            float4 v = *(const float4*)&w[(oBase + r) * K_PRJ + k0 + c];
            As[c+0][r] = v.x; As[c+1][r] = v.y; As[c+2][r] = v.z; As[c+3][r] = v.w;
        }
        {
            int i = tid * 4;
            int r = i >> 6, c = i & 63;
            *(float4*)&Bs[r][c] = *(const float4*)&ao[(k0 + r) * NN + nBase + c];
        }
        __syncthreads();
        #pragma unroll
        for (int kk = 0; kk < 16; kk++) {
            float a0 = As[kk][ty*4+0], a1 = As[kk][ty*4+1];
            float a2 = As[kk][ty*4+2], a3 = As[kk][ty*4+3];
            float b0 = Bs[kk][tx*4+0], b1 = Bs[kk][tx*4+1];
            float b2 = Bs[kk][tx*4+2], b3 = Bs[kk][tx*4+3];
            acc[0][0] = fmaf(a0,b0,acc[0][0]); acc[0][1] = fmaf(a0,b1,acc[0][1]);
            acc[0][2] = fmaf(a0,b2,acc[0][2]); acc[0][3] = fmaf(a0,b3,acc[0][3]);
            acc[1][0] = fmaf(a1,b0,acc[1][0]); acc[1][1] = fmaf(a1,b1,acc[1][1]);
            acc[1][2] = fmaf(a1,b2,acc[1][2]); acc[1][3] = fmaf(a1,b3,acc[1][3]);
            acc[2][0] = fmaf(a2,b0,acc[2][0]); acc[2][1] = fmaf(a2,b1,acc[2][1]);
            acc[2][2] = fmaf(a2,b2,acc[2][2]); acc[2][3] = fmaf(a2,b3,acc[2][3]);
            acc[3][0] = fmaf(a3,b0,acc[3][0]); acc[3][1] = fmaf(a3,b1,acc[3][1]);
            acc[3][2] = fmaf(a3,b2,acc[3][2]); acc[3][3] = fmaf(a3,b3,acc[3][3]);
        }
        __syncthreads();
    }
    #pragma unroll
    for (int i = 0; i < 4; i++) {
        int o = oBase + ty*4 + i;
        #pragma unroll
        for (int j = 0; j < 4; j++) {
            int n = nBase + tx*4 + j;
            out[((size_t)b * CC + o) * NN + n] = acc[i][j];
        }
    }
}

// ---------------------------------------------------------------------------
// K5: training-mode BatchNorm2d, in place. One block per channel.
// ---------------------------------------------------------------------------
__global__ void __launch_bounds__(256) bn_kernel(float* __restrict__ out,
                                                 const float* __restrict__ gamma,
                                                 const float* __restrict__ beta) {
    const int c   = blockIdx.x;
    const int tid = threadIdx.x;
    float s = 0.f, s2 = 0.f;
    #pragma unroll
    for (int b = 0; b < BB; b++) {
        const float* p = out + ((size_t)b * CC + c) * NN;
        for (int i = tid; i < NN; i += 256) {
            float v = p[i];
            s += v; s2 = fmaf(v, v, s2);
        }
    }
    __shared__ float rs[256], rs2[256];
    rs[tid] = s; rs2[tid] = s2;
    __syncthreads();
    for (int off = 128; off > 0; off >>= 1) {
        if (tid < off) { rs[tid] += rs[tid+off]; rs2[tid] += rs2[tid+off]; }
        __syncthreads();
    }
    const float invN  = 1.0f / (BB * NN);
    const float mean  = rs[0] * invN;
    float var         = fmaxf(rs2[0] * invN - mean * mean, 0.f);
    const float scale = rsqrtf(var + 1e-5f) * gamma[c];
    const float shift = beta[c] - mean * scale;
    #pragma unroll
    for (int b = 0; b < BB; b++) {
        float* p = out + ((size_t)b * CC + c) * NN;
        for (int i = tid; i < NN; i += 256)
            p[i] = fmaf(p[i], scale, shift);
    }
}

// ---------------------------------------------------------------------------
extern "C" void kernel_launch(void* const* d_in, const int* in_sizes, int n_in,
                              void* d_out, int out_size) {
    const float* x      = (const float*)d_in[0];
    const float* w_qkv  = (const float*)d_in[1];
    const float* temper = (const float*)d_in[2];
    const float* w_out  = (const float*)d_in[3];
    const float* gamma  = (const float*)d_in[4];
    const float* beta   = (const float*)d_in[5];
    float* out = (float*)d_out;

    qkv_gemm<<<dim3(NN/64, M_QKV/64, BB), 256>>>(x, w_qkv);
    norm_qk<<<(BB*HEADS*NN + 255) / 256, 256>>>();
    attn_kernel<<<dim3(NN/256, HEADS, BB), 256>>>(temper);
    proj_gemm<<<dim3(NN/64, M_PRJ/64, BB), 256>>>(w_out, out);
    bn_kernel<<<CC, 256>>>(out, gamma, beta);
}

// round 2
// speedup vs baseline: 1.5817x; 1.5817x over previous
#include <cuda_runtime.h>
#include <cuda_bf16.h>
#include <math.h>

// Problem constants
#define BB     2
#define CC     512
#define HEADS  8
#define DPH    16
#define TOT    128          // HEADS*DPH
#define NN     2304         // 48*48
#define M_QKV  384          // 3*TOT
#define K_QKV  512
#define M_PRJ  512
#define K_PRJ  128

#define SPLIT  4
#define CHUNK  (NN / SPLIT)  // 576
#define KTILE  192           // 3 tiles per chunk

// Scratch (device globals — no allocation allowed)
__device__ float g_q   [BB*HEADS*NN*DPH];                 // [b][h][n][d]
__device__ float g_k   [BB*HEADS*NN*DPH];
__device__ float g_v   [BB*HEADS*NN*DPH];
__device__ float g_ao  [BB*TOT*NN];                       // [b][t][n]
__device__ float g_part[SPLIT*BB*HEADS*DPH*NN];           // [s][b][h][d][n]
__device__ float g_lsum[SPLIT*BB*HEADS*NN];               // [s][b][h][n]

// ---------------------------------------------------------------------------
// K1: qkv = w_qkv[384,512] @ x[b,512,2304]; scatter into q/k/v [b,h,n,d]
// 128x64 tile, 16 k-step, 256 threads, 8x4 micro-tile.
// ---------------------------------------------------------------------------
__global__ void __launch_bounds__(256) qkv_gemm(const float* __restrict__ x,
                                                const float* __restrict__ w) {
    __shared__ float As[16][128];
    __shared__ float Bs[16][64];
    const int b     = blockIdx.z;
    const int oBase = blockIdx.y * 128;
    const int nBase = blockIdx.x * 64;
    const int tid   = threadIdx.x;
    const int tx    = tid & 15;     // N dir (4 cols)
    const int ty    = tid >> 4;     // M dir (8 rows)
    const float* xb = x + (size_t)b * CC * NN;

    float acc[8][4] = {};
    for (int k0 = 0; k0 < K_QKV; k0 += 16) {
        // A tile: 128 rows(o) x 16 cols(k), stored transposed. 512 float4, 2/thread.
        #pragma unroll
        for (int t = 0; t < 2; t++) {
            int i4 = tid + t * 256;
            int r  = i4 >> 2;           // 0..127
            int c  = (i4 & 3) * 4;      // 0,4,8,12
            float4 v = *(const float4*)&w[(oBase + r) * K_QKV + k0 + c];
            As[c+0][r] = v.x; As[c+1][r] = v.y; As[c+2][r] = v.z; As[c+3][r] = v.w;
        }
        {   // B tile: 16 rows(k) x 64 cols(n). 256 float4, 1/thread.
            int r = tid >> 4, c = (tid & 15) * 4;
            *(float4*)&Bs[r][c] = *(const float4*)&xb[(k0 + r) * NN + nBase + c];
        }
        __syncthreads();
        #pragma unroll
        for (int kk = 0; kk < 16; kk++) {
            float a[8];
            *(float4*)&a[0] = *(const float4*)&As[kk][ty*8];
            *(float4*)&a[4] = *(const float4*)&As[kk][ty*8+4];
            float4 bv = *(const float4*)&Bs[kk][tx*4];
            #pragma unroll
            for (int i = 0; i < 8; i++) {
                acc[i][0] = fmaf(a[i], bv.x, acc[i][0]);
                acc[i][1] = fmaf(a[i], bv.y, acc[i][1]);
                acc[i][2] = fmaf(a[i], bv.z, acc[i][2]);
                acc[i][3] = fmaf(a[i], bv.w, acc[i][3]);
            }
        }
        __syncthreads();
    }
    #pragma unroll
    for (int i = 0; i < 8; i++) {
        int o    = oBase + ty*8 + i;
        int part = o >> 7;          // 0=q,1=k,2=v
        int t    = o & 127;
        int h    = t >> 4, d = t & 15;
        #pragma unroll
        for (int j = 0; j < 4; j++) {
            int n = nBase + tx*4 + j;
            int idx = ((b*HEADS + h)*NN + n)*DPH + d;
            float val = acc[i][j];
            if      (part == 0) g_q[idx] = val;
            else if (part == 1) g_k[idx] = val;
            else                g_v[idx] = val;
        }
    }
}

// ---------------------------------------------------------------------------
// K2: L2-normalize q and k rows (over dph=16), in place. Vectorized.
// ---------------------------------------------------------------------------
__global__ void __launch_bounds__(256) norm_qk() {
    int i = blockIdx.x * 256 + threadIdx.x;
    if (i >= BB*HEADS*NN) return;
    #pragma unroll
    for (int which = 0; which < 2; which++) {
        float4* p = (float4*)((which ? g_k : g_q) + (size_t)i * DPH);
        float4 a = p[0], b = p[1], c = p[2], d = p[3];
        float s = a.x*a.x + a.y*a.y + a.z*a.z + a.w*a.w
                + b.x*b.x + b.y*b.y + b.z*b.z + b.w*b.w
                + c.x*c.x + c.y*c.y + c.z*c.z + c.w*c.w
                + d.x*d.x + d.y*d.y + d.z*d.z + d.w*d.w;
        float inv = 1.0f / fmaxf(sqrtf(s), 1e-12f);
        a.x*=inv; a.y*=inv; a.z*=inv; a.w*=inv;
        b.x*=inv; b.y*=inv; b.z*=inv; b.w*=inv;
        c.x*=inv; c.y*=inv; c.z*=inv; c.w*=inv;
        d.x*=inv; d.y*=inv; d.z*=inv; d.w*=inv;
        p[0]=a; p[1]=b; p[2]=c; p[3]=d;
    }
}

// ---------------------------------------------------------------------------
// K3: attention, no online max (scores bounded: |q.k| <= 1 after L2 norm,
// constant shift cancels in acc/l). 4-way key split for occupancy.
// One thread = one query; K/V tiles in SMEM (broadcast reads).
// ---------------------------------------------------------------------------
__global__ void __launch_bounds__(256) attn_kernel(const float* __restrict__ temperature) {
    __shared__ float Ks[KTILE*16];
    __shared__ float Vs[KTILE*16];
    const int b     = blockIdx.z;
    const int h     = blockIdx.y;
    const int split = blockIdx.x / (NN/256);        // 0..3
    const int qblk  = blockIdx.x % (NN/256);        // 0..8
    const int tid   = threadIdx.x;
    const int n     = qblk * 256 + tid;
    const float temp = temperature[h];
    const int base  = (b*HEADS + h) * NN * DPH;
    const int cstart = split * CHUNK;

    float q[16];
    {
        const float4* qp = (const float4*)(g_q + base + n*DPH);
        *(float4*)&q[0] = qp[0]; *(float4*)&q[4] = qp[1];
        *(float4*)&q[8] = qp[2]; *(float4*)&q[12] = qp[3];
        #pragma unroll
        for (int d = 0; d < 16; d++) q[d] *= temp;
    }

    float l = 0.f;
    float acc[16] = {};

    for (int t0 = 0; t0 < CHUNK; t0 += KTILE) {
        __syncthreads();
        const float4* kg = (const float4*)(g_k + base + (cstart + t0)*DPH);
        const float4* vg = (const float4*)(g_v + base + (cstart + t0)*DPH);
        #pragma unroll
        for (int i = 0; i < 3; i++) {
            ((float4*)Ks)[tid + i*256] = kg[tid + i*256];
            ((float4*)Vs)[tid + i*256] = vg[tid + i*256];
        }
        __syncthreads();
        #pragma unroll 2
        for (int j = 0; j < KTILE; j++) {
            const float4* kr = (const float4*)&Ks[j*16];
            float4 k0 = kr[0], k1 = kr[1], k2 = kr[2], k3 = kr[3];
            // 4 parallel partial dot chains
            float s0 = q[0]*k0.x  + q[1]*k0.y  + q[2]*k0.z  + q[3]*k0.w;
            float s1 = q[4]*k1.x  + q[5]*k1.y  + q[6]*k1.z  + q[7]*k1.w;
            float s2 = q[8]*k2.x  + q[9]*k2.y  + q[10]*k2.z + q[11]*k2.w;
            float s3 = q[12]*k3.x + q[13]*k3.y + q[14]*k3.z + q[15]*k3.w;
            float p = __expf((s0 + s1) + (s2 + s3));
            l += p;
            const float4* vr = (const float4*)&Vs[j*16];
            float4 v0 = vr[0], v1 = vr[1], v2 = vr[2], v3 = vr[3];
            acc[0]  = fmaf(p, v0.x, acc[0]);  acc[1]  = fmaf(p, v0.y, acc[1]);
            acc[2]  = fmaf(p, v0.z, acc[2]);  acc[3]  = fmaf(p, v0.w, acc[3]);
            acc[4]  = fmaf(p, v1.x, acc[4]);  acc[5]  = fmaf(p, v1.y, acc[5]);
            acc[6]  = fmaf(p, v1.z, acc[6]);  acc[7]  = fmaf(p, v1.w, acc[7]);
            acc[8]  = fmaf(p, v2.x, acc[8]);  acc[9]  = fmaf(p, v2.y, acc[9]);
            acc[10] = fmaf(p, v2.z, acc[10]); acc[11] = fmaf(p, v2.w, acc[11]);
            acc[12] = fmaf(p, v3.x, acc[12]); acc[13] = fmaf(p, v3.y, acc[13]);
            acc[14] = fmaf(p, v3.z, acc[14]); acc[15] = fmaf(p, v3.w, acc[15]);
        }
    }
    // partials: [s][b][h][d][n] — coalesced over n
    const int bh = b*HEADS + h;
    float* pp = g_part + ((size_t)(split*BB*HEADS + bh) * DPH) * NN + n;
    #pragma unroll
    for (int d = 0; d < 16; d++) pp[(size_t)d * NN] = acc[d];
    g_lsum[(size_t)(split*BB*HEADS + bh) * NN + n] = l;
}

// ---------------------------------------------------------------------------
// K3b: combine split partials, normalize, write g_ao [b][t][n]
// ---------------------------------------------------------------------------
__global__ void __launch_bounds__(256) combine_kernel() {
    int i = blockIdx.x * 256 + threadIdx.x;
    if (i >= BB*HEADS*NN) return;
    const int n  = i % NN;
    const int bh = i / NN;
    float acc[16] = {};
    float l = 0.f;
    #pragma unroll
    for (int s = 0; s < SPLIT; s++) {
        const float* pp = g_part + ((size_t)(s*BB*HEADS + bh) * DPH) * NN + n;
        #pragma unroll
        for (int d = 0; d < 16; d++) acc[d] += pp[(size_t)d * NN];
        l += g_lsum[(size_t)(s*BB*HEADS + bh) * NN + n];
    }
    const float inv = 1.0f / l;
    #pragma unroll
    for (int d = 0; d < 16; d++)
        g_ao[(size_t)(bh*DPH + d) * NN + n] = acc[d] * inv;
}

// ---------------------------------------------------------------------------
// K4: projection  y[b,c,n] = w_out[c,t] @ ao[b,t,n]   (M=512, K=128, N=2304)
// 128x64 tile, 8x4 micro-tile.
// ---------------------------------------------------------------------------
__global__ void __launch_bounds__(256) proj_gemm(const float* __restrict__ w,
                                                 float* __restrict__ out) {
    __shared__ float As[16][128];
    __shared__ float Bs[16][64];
    const int b     = blockIdx.z;
    const int oBase = blockIdx.y * 128;
    const int nBase = blockIdx.x * 64;
    const int tid   = threadIdx.x;
    const int tx    = tid & 15;
    const int ty    = tid >> 4;
    const float* ao = g_ao + (size_t)b * TOT * NN;

    float acc[8][4] = {};
    for (int k0 = 0; k0 < K_PRJ; k0 += 16) {
        #pragma unroll
        for (int t = 0; t < 2; t++) {
            int i4 = tid + t * 256;
            int r  = i4 >> 2;
            int c  = (i4 & 3) * 4;
            float4 v = *(const float4*)&w[(oBase + r) * K_PRJ + k0 + c];
            As[c+0][r] = v.x; As[c+1][r] = v.y; As[c+2][r] = v.z; As[c+3][r] = v.w;
        }
        {
            int r = tid >> 4, c = (tid & 15) * 4;
            *(float4*)&Bs[r][c] = *(const float4*)&ao[(k0 + r) * NN + nBase + c];
        }
        __syncthreads();
        #pragma unroll
        for (int kk = 0; kk < 16; kk++) {
            float a[8];
            *(float4*)&a[0] = *(const float4*)&As[kk][ty*8];
            *(float4*)&a[4] = *(const float4*)&As[kk][ty*8+4];
            float4 bv = *(const float4*)&Bs[kk][tx*4];
            #pragma unroll
            for (int i = 0; i < 8; i++) {
                acc[i][0] = fmaf(a[i], bv.x, acc[i][0]);
                acc[i][1] = fmaf(a[i], bv.y, acc[i][1]);
                acc[i][2] = fmaf(a[i], bv.z, acc[i][2]);
                acc[i][3] = fmaf(a[i], bv.w, acc[i][3]);
            }
        }
        __syncthreads();
    }
    #pragma unroll
    for (int i = 0; i < 8; i++) {
        int o = oBase + ty*8 + i;
        #pragma unroll
        for (int j = 0; j < 4; j++) {
            int n = nBase + tx*4 + j;
            out[((size_t)b * CC + o) * NN + n] = acc[i][j];
        }
    }
}

// ---------------------------------------------------------------------------
// K5: training-mode BatchNorm2d, in place. One block per channel.
// ---------------------------------------------------------------------------
__global__ void __launch_bounds__(256) bn_kernel(float* __restrict__ out,
                                                 const float* __restrict__ gamma,
                                                 const float* __restrict__ beta) {
    const int c   = blockIdx.x;
    const int tid = threadIdx.x;
    float s = 0.f, s2 = 0.f;
    #pragma unroll
    for (int b = 0; b < BB; b++) {
        const float* p = out + ((size_t)b * CC + c) * NN;
        for (int i = tid; i < NN; i += 256) {
            float v = p[i];
            s += v; s2 = fmaf(v, v, s2);
        }
    }
    __shared__ float rs[256], rs2[256];
    rs[tid] = s; rs2[tid] = s2;
    __syncthreads();
    for (int off = 128; off > 0; off >>= 1) {
        if (tid < off) { rs[tid] += rs[tid+off]; rs2[tid] += rs2[tid+off]; }
        __syncthreads();
    }
    const float invN  = 1.0f / (BB * NN);
    const float mean  = rs[0] * invN;
    float var         = fmaxf(rs2[0] * invN - mean * mean, 0.f);
    const float scale = rsqrtf(var + 1e-5f) * gamma[c];
    const float shift = beta[c] - mean * scale;
    #pragma unroll
    for (int b = 0; b < BB; b++) {
        float* p = out + ((size_t)b * CC + c) * NN;
        for (int i = tid; i < NN; i += 256)
            p[i] = fmaf(p[i], scale, shift);
    }
}

// ---------------------------------------------------------------------------
extern "C" void kernel_launch(void* const* d_in, const int* in_sizes, int n_in,
                              void* d_out, int out_size) {
    const float* x      = (const float*)d_in[0];
    const float* w_qkv  = (const float*)d_in[1];
    const float* temper = (const float*)d_in[2];
    const float* w_out  = (const float*)d_in[3];
    const float* gamma  = (const float*)d_in[4];
    const float* beta   = (const float*)d_in[5];
    float* out = (float*)d_out;

    qkv_gemm<<<dim3(NN/64, M_QKV/128, BB), 256>>>(x, w_qkv);
    norm_qk<<<(BB*HEADS*NN + 255) / 256, 256>>>();
    attn_kernel<<<dim3((NN/256)*SPLIT, HEADS, BB), 256>>>(temper);
    combine_kernel<<<(BB*HEADS*NN + 255) / 256, 256>>>();
    proj_gemm<<<dim3(NN/64, M_PRJ/128, BB), 256>>>(w_out, out);
    bn_kernel<<<CC, 256>>>(out, gamma, beta);
}

// round 4
// speedup vs baseline: 2.6479x; 1.6741x over previous
#include <cuda_runtime.h>
#include <cuda_bf16.h>
#include <math.h>
#include <stdint.h>

// Problem constants
#define BB     2
#define CC     512
#define HEADS  8
#define DPH    16
#define TOT    128          // HEADS*DPH
#define NN     2304         // 48*48
#define M_QKV  384          // 3*TOT
#define K_QKV  512
#define M_PRJ  512
#define K_PRJ  128

// Scratch (device globals — no allocation allowed)
__device__ float g_q [BB*HEADS*NN*DPH];   // [b][h][n][d]
__device__ float g_k [BB*HEADS*NN*DPH];
__device__ float g_v [BB*HEADS*NN*DPH];
__device__ float g_ao[BB*TOT*NN];         // [b][t][n], t = h*16+d

__device__ __forceinline__ uint32_t f2tf32(float f) {
    uint32_t u;
    asm("cvt.rna.tf32.f32 %0, %1;" : "=r"(u) : "f"(f));
    return u;
}
__device__ __forceinline__ float tf32_round(float f) {
    uint32_t u = f2tf32(f);
    return __uint_as_float(u);
}
__device__ __forceinline__ void mma_tf32(float& c0, float& c1, float& c2, float& c3,
                                         uint32_t a0, uint32_t a1, uint32_t a2, uint32_t a3,
                                         uint32_t b0, uint32_t b1) {
    asm volatile("mma.sync.aligned.m16n8k8.row.col.f32.tf32.tf32.f32 "
                 "{%0,%1,%2,%3}, {%4,%5,%6,%7}, {%8,%9}, {%0,%1,%2,%3};"
                 : "+f"(c0), "+f"(c1), "+f"(c2), "+f"(c3)
                 : "r"(a0), "r"(a1), "r"(a2), "r"(a3), "r"(b0), "r"(b1));
}

// ---------------------------------------------------------------------------
// K1: qkv = w_qkv[384,512] @ x[b,512,2304]; scatter into q/k/v [b,h,n,d]
// 128x64 tile, 16 k-step, 256 threads, 8x4 micro-tile.
// ---------------------------------------------------------------------------
__global__ void __launch_bounds__(256) qkv_gemm(const float* __restrict__ x,
                                                const float* __restrict__ w) {
    __shared__ float As[16][128];
    __shared__ float Bs[16][64];
    const int b     = blockIdx.z;
    const int oBase = blockIdx.y * 128;
    const int nBase = blockIdx.x * 64;
    const int tid   = threadIdx.x;
    const int tx    = tid & 15;
    const int ty    = tid >> 4;
    const float* xb = x + (size_t)b * CC * NN;

    float acc[8][4] = {};
    for (int k0 = 0; k0 < K_QKV; k0 += 16) {
        #pragma unroll
        for (int t = 0; t < 2; t++) {
            int i4 = tid + t * 256;
            int r  = i4 >> 2;
            int c  = (i4 & 3) * 4;
            float4 v = *(const float4*)&w[(oBase + r) * K_QKV + k0 + c];
            As[c+0][r] = v.x; As[c+1][r] = v.y; As[c+2][r] = v.z; As[c+3][r] = v.w;
        }
        {
            int r = tid >> 4, c = (tid & 15) * 4;
            *(float4*)&Bs[r][c] = *(const float4*)&xb[(k0 + r) * NN + nBase + c];
        }
        __syncthreads();
        #pragma unroll
        for (int kk = 0; kk < 16; kk++) {
            float a[8];
            *(float4*)&a[0] = *(const float4*)&As[kk][ty*8];
            *(float4*)&a[4] = *(const float4*)&As[kk][ty*8+4];
            float4 bv = *(const float4*)&Bs[kk][tx*4];
            #pragma unroll
            for (int i = 0; i < 8; i++) {
                acc[i][0] = fmaf(a[i], bv.x, acc[i][0]);
                acc[i][1] = fmaf(a[i], bv.y, acc[i][1]);
                acc[i][2] = fmaf(a[i], bv.z, acc[i][2]);
                acc[i][3] = fmaf(a[i], bv.w, acc[i][3]);
            }
        }
        __syncthreads();
    }
    #pragma unroll
    for (int i = 0; i < 8; i++) {
        int o    = oBase + ty*8 + i;
        int part = o >> 7;          // 0=q,1=k,2=v
        int t    = o & 127;
        int h    = t >> 4, d = t & 15;
        #pragma unroll
        for (int j = 0; j < 4; j++) {
            int n = nBase + tx*4 + j;
            int idx = ((b*HEADS + h)*NN + n)*DPH + d;
            float val = acc[i][j];
            if      (part == 0) g_q[idx] = val;
            else if (part == 1) g_k[idx] = val;
            else                g_v[idx] = val;
        }
    }
}

// ---------------------------------------------------------------------------
// K2: L2-normalize q and k rows (over dph=16), in place. Vectorized.
// ---------------------------------------------------------------------------
__global__ void __launch_bounds__(256) norm_qk() {
    int i = blockIdx.x * 256 + threadIdx.x;
    if (i >= BB*HEADS*NN) return;
    #pragma unroll
    for (int which = 0; which < 2; which++) {
        float4* p = (float4*)((which ? g_k : g_q) + (size_t)i * DPH);
        float4 a = p[0], b = p[1], c = p[2], d = p[3];
        float s = a.x*a.x + a.y*a.y + a.z*a.z + a.w*a.w
                + b.x*b.x + b.y*b.y + b.z*b.z + b.w*b.w
                + c.x*c.x + c.y*c.y + c.z*c.z + c.w*c.w
                + d.x*d.x + d.y*d.y + d.z*d.z + d.w*d.w;
        float inv = 1.0f / fmaxf(sqrtf(s), 1e-12f);
        a.x*=inv; a.y*=inv; a.z*=inv; a.w*=inv;
        b.x*=inv; b.y*=inv; b.z*=inv; b.w*=inv;
        c.x*=inv; c.y*=inv; c.z*=inv; c.w*=inv;
        d.x*=inv; d.y*=inv; d.z*=inv; d.w*=inv;
        p[0]=a; p[1]=b; p[2]=c; p[3]=d;
    }
}

// ---------------------------------------------------------------------------
// K3: attention via tf32 mma.sync (m16n8k8). No online max (|q.k|<=1 after
// L2 norm; constant shift cancels). Block = 256 thr = 8 warps x 16 queries.
// K staged in smem stride 20, V stride 24 (conflict-free B-fragment reads).
// C->A fragment relayout for P done with shuffles (no smem round-trip).
// ---------------------------------------------------------------------------
#define KSTR 20
#define VSTR 24
__global__ void __launch_bounds__(256) attn_mma(const float* __restrict__ temperature) {
    __shared__ float Ks[128*KSTR];
    __shared__ float Vs[128*VSTR];
    const int b    = blockIdx.z;
    const int h    = blockIdx.y;
    const int tid  = threadIdx.x;
    const int wid  = tid >> 5;
    const int lane = tid & 31;
    const int gr   = lane >> 2;      // group row 0..7
    const int ct   = lane & 3;       // thread-in-group 0..3
    const float temp = __ldg(&temperature[h]);
    const int base = (b*HEADS + h) * NN * DPH;
    const int qw   = blockIdx.x * 128 + wid * 16;   // warp query base

    // Q fragments: A of S-mma, 2 k-halves (d 0..7, 8..15), temp folded.
    uint32_t qa[2][4];
    #pragma unroll
    for (int dh = 0; dh < 2; dh++) {
        qa[dh][0] = f2tf32(g_q[base + (qw+gr  )*16 + dh*8 + ct    ] * temp);
        qa[dh][1] = f2tf32(g_q[base + (qw+gr+8)*16 + dh*8 + ct    ] * temp);
        qa[dh][2] = f2tf32(g_q[base + (qw+gr  )*16 + dh*8 + ct + 4] * temp);
        qa[dh][3] = f2tf32(g_q[base + (qw+gr+8)*16 + dh*8 + ct + 4] * temp);
    }

    float out0[4] = {};   // d 0..7
    float out1[4] = {};   // d 8..15
    float l0 = 0.f, l1 = 0.f;
    const uint32_t* ksu = (const uint32_t*)Ks;
    const uint32_t* vsu = (const uint32_t*)Vs;
    const int koff = gr * KSTR + ct;   // + kb*8*KSTR + dh*8 (+4)
    const int voff = ct * VSTR + gr;   // + kb*8*VSTR + dh*8 ; b1: +4*VSTR
    const int sidx = (lane & ~3) | (ct >> 1);
    const bool odd = (ct & 1);

    for (int t0 = 0; t0 < NN; t0 += 128) {
        __syncthreads();
        {   // stage K,V tiles (128 rows x 16), tf32-rounded
            const float4* kg = (const float4*)(g_k + base + t0*16);
            const float4* vg = (const float4*)(g_v + base + t0*16);
            #pragma unroll
            for (int t = 0; t < 2; t++) {
                int i4 = tid + t * 256;
                int r = i4 >> 2, c = (i4 & 3) * 4;
                float4 kv = kg[i4];
                kv.x = tf32_round(kv.x); kv.y = tf32_round(kv.y);
                kv.z = tf32_round(kv.z); kv.w = tf32_round(kv.w);
                *(float4*)&Ks[r*KSTR + c] = kv;
                float4 vv = vg[i4];
                vv.x = tf32_round(vv.x); vv.y = tf32_round(vv.y);
                vv.z = tf32_round(vv.z); vv.w = tf32_round(vv.w);
                *(float4*)&Vs[r*VSTR + c] = vv;
            }
        }
        __syncthreads();
        #pragma unroll 8
        for (int kb = 0; kb < 16; kb++) {
            // ---- scores: S[16q x 8keys] = Q . K^T
            float s0 = 0.f, s1 = 0.f, s2 = 0.f, s3 = 0.f;
            {
                int ka = kb*8*KSTR + koff;
                mma_tf32(s0,s1,s2,s3, qa[0][0],qa[0][1],qa[0][2],qa[0][3],
                         ksu[ka], ksu[ka+4]);
                mma_tf32(s0,s1,s2,s3, qa[1][0],qa[1][1],qa[1][2],qa[1][3],
                         ksu[ka+8], ksu[ka+12]);
            }
            // ---- softmax numerator
            float p0 = __expf(s0), p1 = __expf(s1);
            float p2 = __expf(s2), p3 = __expf(s3);
            l0 += p0 + p1;
            l1 += p2 + p3;
            // ---- C-frag -> A-frag relayout via shuffles
            float v00 = __shfl_sync(0xffffffffu, p0, sidx);
            float v01 = __shfl_sync(0xffffffffu, p1, sidx);
            float v02 = __shfl_sync(0xffffffffu, p0, sidx + 2);
            float v03 = __shfl_sync(0xffffffffu, p1, sidx + 2);
            float v10 = __shfl_sync(0xffffffffu, p2, sidx);
            float v11 = __shfl_sync(0xffffffffu, p3, sidx);
            float v12 = __shfl_sync(0xffffffffu, p2, sidx + 2);
            float v13 = __shfl_sync(0xffffffffu, p3, sidx + 2);
            uint32_t pa0 = f2tf32(odd ? v01 : v00);
            uint32_t pa2 = f2tf32(odd ? v03 : v02);
            uint32_t pa1 = f2tf32(odd ? v11 : v10);
            uint32_t pa3 = f2tf32(odd ? v13 : v12);
            // ---- out += P . V
            {
                int va = kb*8*VSTR + voff;
                mma_tf32(out0[0],out0[1],out0[2],out0[3], pa0,pa1,pa2,pa3,
                         vsu[va], vsu[va + 4*VSTR]);
                mma_tf32(out1[0],out1[1],out1[2],out1[3], pa0,pa1,pa2,pa3,
                         vsu[va+8], vsu[va + 4*VSTR + 8]);
            }
        }
    }
    // reduce softmax denominators across the quad
    l0 += __shfl_xor_sync(0xffffffffu, l0, 1);
    l0 += __shfl_xor_sync(0xffffffffu, l0, 2);
    l1 += __shfl_xor_sync(0xffffffffu, l1, 1);
    l1 += __shfl_xor_sync(0xffffffffu, l1, 2);
    const float inv0 = 1.0f / l0;
    const float inv1 = 1.0f / l1;

    // write g_ao[b][h*16+d][n]
    const int bh16 = (b*HEADS + h) * 16;
    {
        int d0 = 2*ct;
        g_ao[(size_t)(bh16 + d0    )*NN + qw + gr    ] = out0[0] * inv0;
        g_ao[(size_t)(bh16 + d0 + 1)*NN + qw + gr    ] = out0[1] * inv0;
        g_ao[(size_t)(bh16 + d0    )*NN + qw + gr + 8] = out0[2] * inv1;
        g_ao[(size_t)(bh16 + d0 + 1)*NN + qw + gr + 8] = out0[3] * inv1;
        g_ao[(size_t)(bh16 + 8 + d0    )*NN + qw + gr    ] = out1[0] * inv0;
        g_ao[(size_t)(bh16 + 8 + d0 + 1)*NN + qw + gr    ] = out1[1] * inv0;
        g_ao[(size_t)(bh16 + 8 + d0    )*NN + qw + gr + 8] = out1[2] * inv1;
        g_ao[(size_t)(bh16 + 8 + d0 + 1)*NN + qw + gr + 8] = out1[3] * inv1;
    }
}

// ---------------------------------------------------------------------------
// K4: projection  y[b,c,n] = w_out[c,t] @ ao[b,t,n]   (M=512, K=128, N=2304)
// ---------------------------------------------------------------------------
__global__ void __launch_bounds__(256) proj_gemm(const float* __restrict__ w,
                                                 float* __restrict__ out) {
    __shared__ float As[16][128];
    __shared__ float Bs[16][64];
    const int b     = blockIdx.z;
    const int oBase = blockIdx.y * 128;
    const int nBase = blockIdx.x * 64;
    const int tid   = threadIdx.x;
    const int tx    = tid & 15;
    const int ty    = tid >> 4;
    const float* ao = g_ao + (size_t)b * TOT * NN;

    float acc[8][4] = {};
    for (int k0 = 0; k0 < K_PRJ; k0 += 16) {
        #pragma unroll
        for (int t = 0; t < 2; t++) {
            int i4 = tid + t * 256;
            int r  = i4 >> 2;
            int c  = (i4 & 3) * 4;
            float4 v = *(const float4*)&w[(oBase + r) * K_PRJ + k0 + c];
            As[c+0][r] = v.x; As[c+1][r] = v.y; As[c+2][r] = v.z; As[c+3][r] = v.w;
        }
        {
            int r = tid >> 4, c = (tid & 15) * 4;
            *(float4*)&Bs[r][c] = *(const float4*)&ao[(k0 + r) * NN + nBase + c];
        }
        __syncthreads();
        #pragma unroll
        for (int kk = 0; kk < 16; kk++) {
            float a[8];
            *(float4*)&a[0] = *(const float4*)&As[kk][ty*8];
            *(float4*)&a[4] = *(const float4*)&As[kk][ty*8+4];
            float4 bv = *(const float4*)&Bs[kk][tx*4];
            #pragma unroll
            for (int i = 0; i < 8; i++) {
                acc[i][0] = fmaf(a[i], bv.x, acc[i][0]);
                acc[i][1] = fmaf(a[i], bv.y, acc[i][1]);
                acc[i][2] = fmaf(a[i], bv.z, acc[i][2]);
                acc[i][3] = fmaf(a[i], bv.w, acc[i][3]);
            }
        }
        __syncthreads();
    }
    #pragma unroll
    for (int i = 0; i < 8; i++) {
        int o = oBase + ty*8 + i;
        #pragma unroll
        for (int j = 0; j < 4; j++) {
            int n = nBase + tx*4 + j;
            out[((size_t)b * CC + o) * NN + n] = acc[i][j];
        }
    }
}

// ---------------------------------------------------------------------------
// K5: training-mode BatchNorm2d, in place. One block per channel.
// ---------------------------------------------------------------------------
__global__ void __launch_bounds__(256) bn_kernel(float* __restrict__ out,
                                                 const float* __restrict__ gamma,
                                                 const float* __restrict__ beta) {
    const int c   = blockIdx.x;
    const int tid = threadIdx.x;
    float s = 0.f, s2 = 0.f;
    #pragma unroll
    for (int b = 0; b < BB; b++) {
        const float* p = out + ((size_t)b * CC + c) * NN;
        for (int i = tid; i < NN; i += 256) {
            float v = p[i];
            s += v; s2 = fmaf(v, v, s2);
        }
    }
    __shared__ float rs[256], rs2[256];
    rs[tid] = s; rs2[tid] = s2;
    __syncthreads();
    for (int off = 128; off > 0; off >>= 1) {
        if (tid < off) { rs[tid] += rs[tid+off]; rs2[tid] += rs2[tid+off]; }
        __syncthreads();
    }
    const float invN  = 1.0f / (BB * NN);
    const float mean  = rs[0] * invN;
    float var         = fmaxf(rs2[0] * invN - mean * mean, 0.f);
    const float scale = rsqrtf(var + 1e-5f) * gamma[c];
    const float shift = beta[c] - mean * scale;
    #pragma unroll
    for (int b = 0; b < BB; b++) {
        float* p = out + ((size_t)b * CC + c) * NN;
        for (int i = tid; i < NN; i += 256)
            p[i] = fmaf(p[i], scale, shift);
    }
}

// ---------------------------------------------------------------------------
extern "C" void kernel_launch(void* const* d_in, const int* in_sizes, int n_in,
                              void* d_out, int out_size) {
    const float* x      = (const float*)d_in[0];
    const float* w_qkv  = (const float*)d_in[1];
    const float* temper = (const float*)d_in[2];
    const float* w_out  = (const float*)d_in[3];
    const float* gamma  = (const float*)d_in[4];
    const float* beta   = (const float*)d_in[5];
    float* out = (float*)d_out;

    qkv_gemm<<<dim3(NN/64, M_QKV/128, BB), 256>>>(x, w_qkv);
    norm_qk<<<(BB*HEADS*NN + 255) / 256, 256>>>();
    attn_mma<<<dim3(NN/128, HEADS, BB), 256>>>(temper);
    proj_gemm<<<dim3(NN/64, M_PRJ/128, BB), 256>>>(w_out, out);
    bn_kernel<<<CC, 256>>>(out, gamma, beta);
}

// round 6
// speedup vs baseline: 3.3439x; 1.2628x over previous
#include <cuda_runtime.h>
#include <cuda_bf16.h>
#include <math.h>
#include <stdint.h>

// Problem constants
#define BB     2
#define CC     512
#define HEADS  8
#define DPH    16
#define TOT    128          // HEADS*DPH
#define NN     2304         // 48*48
#define M_QKV  384          // 3*TOT
#define K_QKV  512
#define M_PRJ  512
#define K_PRJ  128

// Scratch (device globals — no allocation allowed)
__device__ float g_q [BB*HEADS*NN*DPH];   // [b][h][n][d]  (UNNORMALIZED)
__device__ float g_k [BB*HEADS*NN*DPH];
__device__ float g_v [BB*HEADS*NN*DPH];
__device__ float g_ao[BB*TOT*NN];         // [b][t][n], t = h*16+d

__device__ __forceinline__ uint32_t f2tf32(float f) {
    uint32_t u;
    asm("cvt.rna.tf32.f32 %0, %1;" : "=r"(u) : "f"(f));
    return u;
}
__device__ __forceinline__ float tf32_round(float f) {
    return __uint_as_float(f2tf32(f));
}
__device__ __forceinline__ void mma_tf32(float* c,
                                         const uint32_t* a,
                                         uint32_t b0, uint32_t b1) {
    asm volatile("mma.sync.aligned.m16n8k8.row.col.f32.tf32.tf32.f32 "
                 "{%0,%1,%2,%3}, {%4,%5,%6,%7}, {%8,%9}, {%0,%1,%2,%3};"
                 : "+f"(c[0]), "+f"(c[1]), "+f"(c[2]), "+f"(c[3])
                 : "r"(a[0]), "r"(a[1]), "r"(a[2]), "r"(a[3]), "r"(b0), "r"(b1));
}

// ===========================================================================
// Split-tf32 GEMM (C = A[M,K] @ B[K,N]), block tile 64x64, warp tile 32x16,
// k-chunk 32. 3-MMA hi/lo split => fp32-grade accuracy on tensor pipe.
// A staged [m][k] stride 36 (frag banks 4*gr+ct distinct);
// B staged [k][n] stride 72 (frag banks 8*ct+gr distinct).
// Epilogue lambda: epi(m_global_row, n_global_col, value).
// ===========================================================================
#define AST 36
#define BST 72

template <int KDIM, typename Epi>
__device__ __forceinline__ void gemm_body(const float* __restrict__ A,
                                          const float* __restrict__ B,
                                          Epi epi) {
    __shared__ float Ah[64*AST], Al[64*AST];
    __shared__ float Bh[32*BST], Bl[32*BST];
    const int tid  = threadIdx.x;
    const int lane = tid & 31;
    const int wid  = tid >> 5;
    const int gr   = lane >> 2;
    const int ct   = lane & 3;
    const int wm   = (wid & 1) * 32;
    const int wn   = (wid >> 1) * 16;
    const int mBase = blockIdx.y * 64;
    const int nBase = blockIdx.x * 64;

    int am[2], ak[2], bk[2], bn[2];
    #pragma unroll
    for (int t = 0; t < 2; t++) {
        int i4 = tid + t * 256;
        am[t] = i4 >> 3;  ak[t] = (i4 & 7) << 2;
        bk[t] = i4 >> 4;  bn[t] = (i4 & 15) << 2;
    }
    float4 areg[2], breg[2];
    #pragma unroll
    for (int t = 0; t < 2; t++) {
        areg[t] = *(const float4*)&A[(mBase + am[t]) * KDIM + ak[t]];
        breg[t] = *(const float4*)&B[(size_t)bk[t] * NN + nBase + bn[t]];
    }

    float c[2][2][4] = {};
    for (int ch = 0; ch < KDIM/32; ch++) {
        __syncthreads();
        #pragma unroll
        for (int t = 0; t < 2; t++) {
            float hx = tf32_round(areg[t].x), hy = tf32_round(areg[t].y);
            float hz = tf32_round(areg[t].z), hw = tf32_round(areg[t].w);
            *(float4*)&Ah[am[t]*AST + ak[t]] = make_float4(hx, hy, hz, hw);
            *(float4*)&Al[am[t]*AST + ak[t]] =
                make_float4(tf32_round(areg[t].x - hx), tf32_round(areg[t].y - hy),
                            tf32_round(areg[t].z - hz), tf32_round(areg[t].w - hw));
            float gx = tf32_round(breg[t].x), gy = tf32_round(breg[t].y);
            float gz = tf32_round(breg[t].z), gw = tf32_round(breg[t].w);
            *(float4*)&Bh[bk[t]*BST + bn[t]] = make_float4(gx, gy, gz, gw);
            *(float4*)&Bl[bk[t]*BST + bn[t]] =
                make_float4(tf32_round(breg[t].x - gx), tf32_round(breg[t].y - gy),
                            tf32_round(breg[t].z - gz), tf32_round(breg[t].w - gw));
        }
        __syncthreads();
        if (ch + 1 < KDIM/32) {
            #pragma unroll
            for (int t = 0; t < 2; t++) {
                areg[t] = *(const float4*)&A[(mBase + am[t]) * KDIM + (ch+1)*32 + ak[t]];
                breg[t] = *(const float4*)&B[(size_t)((ch+1)*32 + bk[t]) * NN + nBase + bn[t]];
            }
        }
        #pragma unroll
        for (int k8 = 0; k8 < 4; k8++) {
            const int kk = k8 * 8;
            uint32_t ah[2][4], al2[2][4];
            #pragma unroll
            for (int mt = 0; mt < 2; mt++) {
                int m0 = wm + mt*16;
                ah[mt][0]  = __float_as_uint(Ah[(m0+gr  )*AST + kk+ct  ]);
                ah[mt][1]  = __float_as_uint(Ah[(m0+gr+8)*AST + kk+ct  ]);
                ah[mt][2]  = __float_as_uint(Ah[(m0+gr  )*AST + kk+ct+4]);
                ah[mt][3]  = __float_as_uint(Ah[(m0+gr+8)*AST + kk+ct+4]);
                al2[mt][0] = __float_as_uint(Al[(m0+gr  )*AST + kk+ct  ]);
                al2[mt][1] = __float_as_uint(Al[(m0+gr+8)*AST + kk+ct  ]);
                al2[mt][2] = __float_as_uint(Al[(m0+gr  )*AST + kk+ct+4]);
                al2[mt][3] = __float_as_uint(Al[(m0+gr+8)*AST + kk+ct+4]);
            }
            uint32_t bhf[2][2], blf[2][2];
            #pragma unroll
            for (int nt = 0; nt < 2; nt++) {
                int n0 = wn + nt*8;
                bhf[nt][0] = __float_as_uint(Bh[(kk+ct  )*BST + n0+gr]);
                bhf[nt][1] = __float_as_uint(Bh[(kk+ct+4)*BST + n0+gr]);
                blf[nt][0] = __float_as_uint(Bl[(kk+ct  )*BST + n0+gr]);
                blf[nt][1] = __float_as_uint(Bl[(kk+ct+4)*BST + n0+gr]);
            }
            #pragma unroll
            for (int mt = 0; mt < 2; mt++)
            #pragma unroll
            for (int nt = 0; nt < 2; nt++) {
                mma_tf32(c[mt][nt], ah[mt],  bhf[nt][0], bhf[nt][1]);
                mma_tf32(c[mt][nt], ah[mt],  blf[nt][0], blf[nt][1]);
                mma_tf32(c[mt][nt], al2[mt], bhf[nt][0], bhf[nt][1]);
            }
        }
    }
    #pragma unroll
    for (int mt = 0; mt < 2; mt++)
    #pragma unroll
    for (int nt = 0; nt < 2; nt++)
    #pragma unroll
    for (int e = 0; e < 4; e++) {
        int m = mBase + wm + mt*16 + gr + ((e >= 2) ? 8 : 0);
        int n = nBase + wn + nt*8 + 2*ct + (e & 1);
        epi(m, n, c[mt][nt][e]);
    }
}

// K1: qkv = w_qkv[384,512] @ x[b,512,2304]; scatter into q/k/v [b,h,n,d]
__global__ void __launch_bounds__(256) qkv_mma(const float* __restrict__ x,
                                               const float* __restrict__ w) {
    const int b = blockIdx.z;
    const float* xb = x + (size_t)b * CC * NN;
    gemm_body<K_QKV>(w, xb, [b](int m, int n, float val) {
        int part = m >> 7;              // 0=q,1=k,2=v
        int t2 = m & 127, h = t2 >> 4, d = t2 & 15;
        int idx = ((b*HEADS + h)*NN + n)*DPH + d;
        if      (part == 0) g_q[idx] = val;
        else if (part == 1) g_k[idx] = val;
        else                g_v[idx] = val;
    });
}

// K4: out[b,c,n] = w_out[512,128] @ ao[b,128,2304]
__global__ void __launch_bounds__(256) proj_mma(const float* __restrict__ w,
                                                float* __restrict__ out) {
    const int b = blockIdx.z;
    const float* ao = g_ao + (size_t)b * TOT * NN;
    gemm_body<K_PRJ>(w, ao, [b, out](int m, int n, float val) {
        out[((size_t)b * CC + m) * NN + n] = val;
    });
}

// ===========================================================================
// K3: attention via tf32 mma.sync (m16n8k8), L2-normalization of q,k fused
// (quad-shuffle sum of squares). No online max (|q.k|<=1 after norm).
// exp2 with log2e folded into temperature. Block = 8 warps x 16 queries.
// ===========================================================================
#define KSTR 20
#define VSTR 24
__global__ void __launch_bounds__(256) attn_mma(const float* __restrict__ temperature) {
    __shared__ float Ks[128*KSTR];
    __shared__ float Vs[128*VSTR];
    const int b    = blockIdx.z;
    const int h    = blockIdx.y;
    const int tid  = threadIdx.x;
    const int wid  = tid >> 5;
    const int lane = tid & 31;
    const int gr   = lane >> 2;      // group row 0..7
    const int ct   = lane & 3;       // thread-in-group 0..3
    const float scale = __ldg(&temperature[h]) * 1.4426950408889634f; // temp*log2e
    const int base = (b*HEADS + h) * NN * DPH;
    const int qw   = blockIdx.x * 128 + wid * 16;   // warp query base

    // Q fragments with fused L2-norm: thread holds rows qw+gr / qw+gr+8,
    // cols {ct, ct+4, ct+8, ct+12}; quad shuffles complete each row's sumsq.
    uint32_t qa[2][4];
    {
        const float* q0 = g_q + base + (qw+gr  )*DPH;
        const float* q1 = g_q + base + (qw+gr+8)*DPH;
        float r0[4], r1[4];
        #pragma unroll
        for (int j = 0; j < 4; j++) { r0[j] = q0[ct + 4*j]; r1[j] = q1[ct + 4*j]; }
        float s0 = r0[0]*r0[0] + r0[1]*r0[1] + r0[2]*r0[2] + r0[3]*r0[3];
        float s1 = r1[0]*r1[0] + r1[1]*r1[1] + r1[2]*r1[2] + r1[3]*r1[3];
        s0 += __shfl_xor_sync(0xffffffffu, s0, 1);
        s0 += __shfl_xor_sync(0xffffffffu, s0, 2);
        s1 += __shfl_xor_sync(0xffffffffu, s1, 1);
        s1 += __shfl_xor_sync(0xffffffffu, s1, 2);
        float i0 = scale / fmaxf(sqrtf(s0), 1e-12f);
        float i1 = scale / fmaxf(sqrtf(s1), 1e-12f);
        // qa[dh][0]=row0 col dh*8+ct, [1]=row1 same, [2]=row0 col+4, [3]=row1 col+4
        qa[0][0] = f2tf32(r0[0]*i0); qa[0][1] = f2tf32(r1[0]*i1);
        qa[0][2] = f2tf32(r0[1]*i0); qa[0][3] = f2tf32(r1[1]*i1);
        qa[1][0] = f2tf32(r0[2]*i0); qa[1][1] = f2tf32(r1[2]*i1);
        qa[1][2] = f2tf32(r0[3]*i0); qa[1][3] = f2tf32(r1[3]*i1);
    }

    float out0[4] = {};   // d 0..7
    float out1[4] = {};   // d 8..15
    float l0 = 0.f, l1 = 0.f;
    const uint32_t* ksu = (const uint32_t*)Ks;
    const uint32_t* vsu = (const uint32_t*)Vs;
    const int koff = gr * KSTR + ct;
    const int voff = ct * VSTR + gr;
    const int sidx = (lane & ~3) | (ct >> 1);
    const bool odd = (ct & 1);

    for (int t0 = 0; t0 < NN; t0 += 128) {
        __syncthreads();
        {   // stage K (L2-normalized, tf32) and V (tf32) tiles: 128 rows x 16
            const float4* kg = (const float4*)(g_k + base + t0*16);
            const float4* vg = (const float4*)(g_v + base + t0*16);
            #pragma unroll
            for (int t = 0; t < 2; t++) {
                int i4 = tid + t * 256;
                int r = i4 >> 2, cc4 = (i4 & 3) * 4;
                float4 kv = kg[i4];
                float s = kv.x*kv.x + kv.y*kv.y + kv.z*kv.z + kv.w*kv.w;
                s += __shfl_xor_sync(0xffffffffu, s, 1);
                s += __shfl_xor_sync(0xffffffffu, s, 2);
                float inv = 1.0f / fmaxf(sqrtf(s), 1e-12f);
                kv.x = tf32_round(kv.x * inv); kv.y = tf32_round(kv.y * inv);
                kv.z = tf32_round(kv.z * inv); kv.w = tf32_round(kv.w * inv);
                *(float4*)&Ks[r*KSTR + cc4] = kv;
                float4 vv = vg[i4];
                vv.x = tf32_round(vv.x); vv.y = tf32_round(vv.y);
                vv.z = tf32_round(vv.z); vv.w = tf32_round(vv.w);
                *(float4*)&Vs[r*VSTR + cc4] = vv;
            }
        }
        __syncthreads();
        #pragma unroll 8
        for (int kb = 0; kb < 16; kb++) {
            // ---- scores: S[16q x 8keys] = Q . K^T
            float s[4] = {};
            {
                int ka = kb*8*KSTR + koff;
                mma_tf32(s, qa[0], ksu[ka],   ksu[ka+4]);
                mma_tf32(s, qa[1], ksu[ka+8], ksu[ka+12]);
            }
            // ---- softmax numerator (exp2; scale folded into q)
            float p0 = exp2f(s[0]), p1 = exp2f(s[1]);
            float p2 = exp2f(s[2]), p3 = exp2f(s[3]);
            l0 += p0 + p1;
            l1 += p2 + p3;
            // ---- C-frag -> A-frag relayout via shuffles
            float v00 = __shfl_sync(0xffffffffu, p0, sidx);
            float v01 = __shfl_sync(0xffffffffu, p1, sidx);
            float v02 = __shfl_sync(0xffffffffu, p0, sidx + 2);
            float v03 = __shfl_sync(0xffffffffu, p1, sidx + 2);
            float v10 = __shfl_sync(0xffffffffu, p2, sidx);
            float v11 = __shfl_sync(0xffffffffu, p3, sidx);
            float v12 = __shfl_sync(0xffffffffu, p2, sidx + 2);
            float v13 = __shfl_sync(0xffffffffu, p3, sidx + 2);
            uint32_t pa[4];
            pa[0] = f2tf32(odd ? v01 : v00);
            pa[2] = f2tf32(odd ? v03 : v02);
            pa[1] = f2tf32(odd ? v11 : v10);
            pa[3] = f2tf32(odd ? v13 : v12);
            // ---- out += P . V
            {
                int va = kb*8*VSTR + voff;
                mma_tf32(out0, pa, vsu[va],   vsu[va + 4*VSTR]);
                mma_tf32(out1, pa, vsu[va+8], vsu[va + 4*VSTR + 8]);
            }
        }
    }
    // reduce softmax denominators across the quad
    l0 += __shfl_xor_sync(0xffffffffu, l0, 1);
    l0 += __shfl_xor_sync(0xffffffffu, l0, 2);
    l1 += __shfl_xor_sync(0xffffffffu, l1, 1);
    l1 += __shfl_xor_sync(0xffffffffu, l1, 2);
    const float inv0 = 1.0f / l0;
    const float inv1 = 1.0f / l1;

    // write g_ao[b][h*16+d][n]
    const int bh16 = (b*HEADS + h) * 16;
    {
        int d0 = 2*ct;
        g_ao[(size_t)(bh16 + d0    )*NN + qw + gr    ] = out0[0] * inv0;
        g_ao[(size_t)(bh16 + d0 + 1)*NN + qw + gr    ] = out0[1] * inv0;
        g_ao[(size_t)(bh16 + d0    )*NN + qw + gr + 8] = out0[2] * inv1;
        g_ao[(size_t)(bh16 + d0 + 1)*NN + qw + gr + 8] = out0[3] * inv1;
        g_ao[(size_t)(bh16 + 8 + d0    )*NN + qw + gr    ] = out1[0] * inv0;
        g_ao[(size_t)(bh16 + 8 + d0 + 1)*NN + qw + gr    ] = out1[1] * inv0;
        g_ao[(size_t)(bh16 + 8 + d0    )*NN + qw + gr + 8] = out1[2] * inv1;
        g_ao[(size_t)(bh16 + 8 + d0 + 1)*NN + qw + gr + 8] = out1[3] * inv1;
    }
}

// ---------------------------------------------------------------------------
// K5: training-mode BatchNorm2d, in place. One block per channel.
// ---------------------------------------------------------------------------
__global__ void __launch_bounds__(256) bn_kernel(float* __restrict__ out,
                                                 const float* __restrict__ gamma,
                                                 const float* __restrict__ beta) {
    const int c   = blockIdx.x;
    const int tid = threadIdx.x;
    float s = 0.f, s2 = 0.f;
    #pragma unroll
    for (int b = 0; b < BB; b++) {
        const float* p = out + ((size_t)b * CC + c) * NN;
        for (int i = tid; i < NN; i += 256) {
            float v = p[i];
            s += v; s2 = fmaf(v, v, s2);
        }
    }
    __shared__ float rs[256], rs2[256];
    rs[tid] = s; rs2[tid] = s2;
    __syncthreads();
    for (int off = 128; off > 0; off >>= 1) {
        if (tid < off) { rs[tid] += rs[tid+off]; rs2[tid] += rs2[tid+off]; }
        __syncthreads();
    }
    const float invN  = 1.0f / (BB * NN);
    const float mean  = rs[0] * invN;
    float var         = fmaxf(rs2[0] * invN - mean * mean, 0.f);
    const float scale = rsqrtf(var + 1e-5f) * gamma[c];
    const float shift = beta[c] - mean * scale;
    #pragma unroll
    for (int b = 0; b < BB; b++) {
        float* p = out + ((size_t)b * CC + c) * NN;
        for (int i = tid; i < NN; i += 256)
            p[i] = fmaf(p[i], scale, shift);
    }
}

// ---------------------------------------------------------------------------
extern "C" void kernel_launch(void* const* d_in, const int* in_sizes, int n_in,
                              void* d_out, int out_size) {
    const float* x      = (const float*)d_in[0];
    const float* w_qkv  = (const float*)d_in[1];
    const float* temper = (const float*)d_in[2];
    const float* w_out  = (const float*)d_in[3];
    const float* gamma  = (const float*)d_in[4];
    const float* beta   = (const float*)d_in[5];
    float* out = (float*)d_out;

    qkv_mma <<<dim3(NN/64, M_QKV/64, BB), 256>>>(x, w_qkv);
    attn_mma<<<dim3(NN/128, HEADS, BB), 256>>>(temper);
    proj_mma<<<dim3(NN/64, M_PRJ/64, BB), 256>>>(w_out, out);
    bn_kernel<<<CC, 256>>>(out, gamma, beta);
}

// round 7
// speedup vs baseline: 3.8992x; 1.1661x over previous
#include <cuda_runtime.h>
#include <cuda_bf16.h>
#include <math.h>
#include <stdint.h>

// Problem constants
#define BB     2
#define CC     512
#define HEADS  8
#define DPH    16
#define TOT    128          // HEADS*DPH
#define NN     2304         // 48*48
#define M_QKV  384          // 3*TOT
#define K_QKV  512
#define M_PRJ  512
#define K_PRJ  128

// Scratch (device globals — no allocation allowed)
__device__ float g_q [BB*HEADS*NN*DPH];   // [b][h][n][d]  (UNNORMALIZED)
__device__ float g_k [BB*HEADS*NN*DPH];
__device__ float g_v [BB*HEADS*NN*DPH];
__device__ float g_ao[BB*TOT*NN];         // [b][t][n], t = h*16+d

__device__ __forceinline__ uint32_t f2tf32(float f) {
    uint32_t u;
    asm("cvt.rna.tf32.f32 %0, %1;" : "=r"(u) : "f"(f));
    return u;
}
__device__ __forceinline__ float tf32_round(float f) {
    return __uint_as_float(f2tf32(f));
}
__device__ __forceinline__ void mma_tf32(float* c,
                                         const uint32_t* a,
                                         uint32_t b0, uint32_t b1) {
    asm volatile("mma.sync.aligned.m16n8k8.row.col.f32.tf32.tf32.f32 "
                 "{%0,%1,%2,%3}, {%4,%5,%6,%7}, {%8,%9}, {%0,%1,%2,%3};"
                 : "+f"(c[0]), "+f"(c[1]), "+f"(c[2]), "+f"(c[3])
                 : "r"(a[0]), "r"(a[1]), "r"(a[2]), "r"(a[3]), "r"(b0), "r"(b1));
}
__device__ __forceinline__ void mma_bf16(float* c,
                                         const uint32_t* a,
                                         uint32_t b0, uint32_t b1) {
    asm volatile("mma.sync.aligned.m16n8k16.row.col.f32.bf16.bf16.f32 "
                 "{%0,%1,%2,%3}, {%4,%5,%6,%7}, {%8,%9}, {%0,%1,%2,%3};"
                 : "+f"(c[0]), "+f"(c[1]), "+f"(c[2]), "+f"(c[3])
                 : "r"(a[0]), "r"(a[1]), "r"(a[2]), "r"(a[3]), "r"(b0), "r"(b1));
}
// pack two floats as bf16x2: low half = lo_elem (smaller k), high half = hi_elem
__device__ __forceinline__ uint32_t pack2bf(float lo_elem, float hi_elem) {
    uint32_t r;
    asm("cvt.rn.bf16x2.f32 %0, %1, %2;" : "=r"(r) : "f"(hi_elem), "f"(lo_elem));
    return r;
}
// residual (lo part) of a 2-term bf16 split, given hi packed word + originals
__device__ __forceinline__ uint32_t split_lo2(uint32_t hpk, float e0, float e1) {
    float h0 = __uint_as_float(hpk << 16);
    float h1 = __uint_as_float(hpk & 0xFFFF0000u);
    return pack2bf(e0 - h0, e1 - h1);
}
__device__ __forceinline__ void ldsm_x2_trans(uint32_t& r0, uint32_t& r1, uint32_t saddr) {
    asm volatile("ldmatrix.sync.aligned.m8n8.x2.trans.shared.b16 {%0,%1}, [%2];"
                 : "=r"(r0), "=r"(r1) : "r"(saddr));
}

// ===========================================================================
// Split-bf16 GEMM (C = A[M,K] @ B[K,N]), block tile 64x64, warp tile 32x16,
// k-chunk 32, mma m16n8k16. 3-MMA hi/lo split (Ah*Bh + Ah*Bl + Al*Bh) =>
// ~fp32 accuracy on tensor pipe at half the tf32-split MMA count.
// A staged [m][k] as bf16, row stride 40 (20 words: frag banks gr*20+ct ok).
// B staged [k][n] as bf16, row stride 72 (144B, 16B-aligned rows for ldsm).
// Epilogue lambda: epi(m_global_row, n_global_col, value).
// ===========================================================================
#define AWS 20     // A row stride in 32-bit words (= 40 bf16)
#define BSTRB 72   // B row stride in bf16 elems

template <int KDIM, typename Epi>
__device__ __forceinline__ void gemm_body(const float* __restrict__ A,
                                          const float* __restrict__ B,
                                          Epi epi) {
    __shared__ __align__(16) uint32_t Ah[64*AWS], Al[64*AWS];
    __shared__ __align__(16) __nv_bfloat16 Bh[32*BSTRB], Bl[32*BSTRB];
    const int tid  = threadIdx.x;
    const int lane = tid & 31;
    const int wid  = tid >> 5;
    const int gr   = lane >> 2;
    const int ct   = lane & 3;
    const int wm   = (wid & 1) * 32;
    const int wn   = (wid >> 1) * 16;
    const int mBase = blockIdx.y * 64;
    const int nBase = blockIdx.x * 64;

    int am[2], ak[2], bk[2], bn[2];
    #pragma unroll
    for (int t = 0; t < 2; t++) {
        int i4 = tid + t * 256;
        am[t] = i4 >> 3;  ak[t] = (i4 & 7) << 2;   // A: 64 rows x 32 k (f32x4)
        bk[t] = i4 >> 4;  bn[t] = (i4 & 15) << 2;  // B: 32 k x 64 n  (f32x4)
    }
    float4 areg[2], breg[2];
    #pragma unroll
    for (int t = 0; t < 2; t++) {
        areg[t] = *(const float4*)&A[(mBase + am[t]) * KDIM + ak[t]];
        breg[t] = *(const float4*)&B[(size_t)bk[t] * NN + nBase + bn[t]];
    }

    // ldmatrix row addresses (lane & 15 selects k-row within the 16-row step)
    const int lrow = lane & 15;

    float c[2][2][4] = {};
    for (int ch = 0; ch < KDIM/32; ch++) {
        __syncthreads();
        #pragma unroll
        for (int t = 0; t < 2; t++) {
            // A: split into hi/lo bf16, store packed pairs
            uint32_t ah0 = pack2bf(areg[t].x, areg[t].y);
            uint32_t ah1 = pack2bf(areg[t].z, areg[t].w);
            uint32_t al0 = split_lo2(ah0, areg[t].x, areg[t].y);
            uint32_t al1 = split_lo2(ah1, areg[t].z, areg[t].w);
            int awi = am[t]*AWS + (ak[t] >> 1);
            *(uint2*)&Ah[awi] = make_uint2(ah0, ah1);
            *(uint2*)&Al[awi] = make_uint2(al0, al1);
            // B: same split, [k][n] layout
            uint32_t bh0 = pack2bf(breg[t].x, breg[t].y);
            uint32_t bh1 = pack2bf(breg[t].z, breg[t].w);
            uint32_t bl0 = split_lo2(bh0, breg[t].x, breg[t].y);
            uint32_t bl1 = split_lo2(bh1, breg[t].z, breg[t].w);
            int bwi = (bk[t]*BSTRB + bn[t]) >> 1;
            *(uint2*)&((uint32_t*)Bh)[bwi] = make_uint2(bh0, bh1);
            *(uint2*)&((uint32_t*)Bl)[bwi] = make_uint2(bl0, bl1);
        }
        __syncthreads();
        if (ch + 1 < KDIM/32) {
            #pragma unroll
            for (int t = 0; t < 2; t++) {
                areg[t] = *(const float4*)&A[(mBase + am[t]) * KDIM + (ch+1)*32 + ak[t]];
                breg[t] = *(const float4*)&B[(size_t)((ch+1)*32 + bk[t]) * NN + nBase + bn[t]];
            }
        }
        #pragma unroll
        for (int s = 0; s < 2; s++) {           // two k16 steps per chunk
            const int kwo = s * 8;              // word offset in A row
            const int kro = s * 16;             // k-row offset in B
            uint32_t ah[2][4], al2[2][4];
            #pragma unroll
            for (int mt = 0; mt < 2; mt++) {
                int m0 = wm + mt*16;
                int w00 = (m0+gr  )*AWS + kwo + ct;
                int w10 = (m0+gr+8)*AWS + kwo + ct;
                ah[mt][0]  = Ah[w00];     ah[mt][1]  = Ah[w10];
                ah[mt][2]  = Ah[w00 + 4]; ah[mt][3]  = Ah[w10 + 4];
                al2[mt][0] = Al[w00];     al2[mt][1] = Al[w10];
                al2[mt][2] = Al[w00 + 4]; al2[mt][3] = Al[w10 + 4];
            }
            uint32_t bhf[2][2], blf[2][2];
            #pragma unroll
            for (int nt = 0; nt < 2; nt++) {
                int n0 = wn + nt*8;
                uint32_t ah_addr = (uint32_t)__cvta_generic_to_shared(
                    &Bh[(kro + lrow)*BSTRB + n0]);
                uint32_t al_addr = (uint32_t)__cvta_generic_to_shared(
                    &Bl[(kro + lrow)*BSTRB + n0]);
                ldsm_x2_trans(bhf[nt][0], bhf[nt][1], ah_addr);
                ldsm_x2_trans(blf[nt][0], blf[nt][1], al_addr);
            }
            #pragma unroll
            for (int mt = 0; mt < 2; mt++)
            #pragma unroll
            for (int nt = 0; nt < 2; nt++) {
                mma_bf16(c[mt][nt], ah[mt],  bhf[nt][0], bhf[nt][1]);
                mma_bf16(c[mt][nt], ah[mt],  blf[nt][0], blf[nt][1]);
                mma_bf16(c[mt][nt], al2[mt], bhf[nt][0], bhf[nt][1]);
            }
        }
    }
    #pragma unroll
    for (int mt = 0; mt < 2; mt++)
    #pragma unroll
    for (int nt = 0; nt < 2; nt++)
    #pragma unroll
    for (int e = 0; e < 4; e++) {
        int m = mBase + wm + mt*16 + gr + ((e >= 2) ? 8 : 0);
        int n = nBase + wn + nt*8 + 2*ct + (e & 1);
        epi(m, n, c[mt][nt][e]);
    }
}

// K1: qkv = w_qkv[384,512] @ x[b,512,2304]; scatter into q/k/v [b,h,n,d]
__global__ void __launch_bounds__(256) qkv_mma(const float* __restrict__ x,
                                               const float* __restrict__ w) {
    const int b = blockIdx.z;
    const float* xb = x + (size_t)b * CC * NN;
    gemm_body<K_QKV>(w, xb, [b](int m, int n, float val) {
        int part = m >> 7;              // 0=q,1=k,2=v
        int t2 = m & 127, h = t2 >> 4, d = t2 & 15;
        int idx = ((b*HEADS + h)*NN + n)*DPH + d;
        if      (part == 0) g_q[idx] = val;
        else if (part == 1) g_k[idx] = val;
        else                g_v[idx] = val;
    });
}

// K4: out[b,c,n] = w_out[512,128] @ ao[b,128,2304]
__global__ void __launch_bounds__(256) proj_mma(const float* __restrict__ w,
                                                float* __restrict__ out) {
    const int b = blockIdx.z;
    const float* ao = g_ao + (size_t)b * TOT * NN;
    gemm_body<K_PRJ>(w, ao, [b, out](int m, int n, float val) {
        out[((size_t)b * CC + m) * NN + n] = val;
    });
}

// ===========================================================================
// K3: attention via tf32 mma.sync (m16n8k8), L2-normalization of q,k fused
// (quad-shuffle sum of squares). No online max (|q.k|<=1 after norm).
// exp2 with log2e folded into temperature. Block = 8 warps x 16 queries.
// (UNCHANGED from R6 — numerically load-bearing.)
// ===========================================================================
#define KSTR 20
#define VSTR 24
__global__ void __launch_bounds__(256) attn_mma(const float* __restrict__ temperature) {
    __shared__ float Ks[128*KSTR];
    __shared__ float Vs[128*VSTR];
    const int b    = blockIdx.z;
    const int h    = blockIdx.y;
    const int tid  = threadIdx.x;
    const int wid  = tid >> 5;
    const int lane = tid & 31;
    const int gr   = lane >> 2;      // group row 0..7
    const int ct   = lane & 3;       // thread-in-group 0..3
    const float scale = __ldg(&temperature[h]) * 1.4426950408889634f; // temp*log2e
    const int base = (b*HEADS + h) * NN * DPH;
    const int qw   = blockIdx.x * 128 + wid * 16;   // warp query base

    uint32_t qa[2][4];
    {
        const float* q0 = g_q + base + (qw+gr  )*DPH;
        const float* q1 = g_q + base + (qw+gr+8)*DPH;
        float r0[4], r1[4];
        #pragma unroll
        for (int j = 0; j < 4; j++) { r0[j] = q0[ct + 4*j]; r1[j] = q1[ct + 4*j]; }
        float s0 = r0[0]*r0[0] + r0[1]*r0[1] + r0[2]*r0[2] + r0[3]*r0[3];
        float s1 = r1[0]*r1[0] + r1[1]*r1[1] + r1[2]*r1[2] + r1[3]*r1[3];
        s0 += __shfl_xor_sync(0xffffffffu, s0, 1);
        s0 += __shfl_xor_sync(0xffffffffu, s0, 2);
        s1 += __shfl_xor_sync(0xffffffffu, s1, 1);
        s1 += __shfl_xor_sync(0xffffffffu, s1, 2);
        float i0 = scale / fmaxf(sqrtf(s0), 1e-12f);
        float i1 = scale / fmaxf(sqrtf(s1), 1e-12f);
        qa[0][0] = f2tf32(r0[0]*i0); qa[0][1] = f2tf32(r1[0]*i1);
        qa[0][2] = f2tf32(r0[1]*i0); qa[0][3] = f2tf32(r1[1]*i1);
        qa[1][0] = f2tf32(r0[2]*i0); qa[1][1] = f2tf32(r1[2]*i1);
        qa[1][2] = f2tf32(r0[3]*i0); qa[1][3] = f2tf32(r1[3]*i1);
    }

    float out0[4] = {};   // d 0..7
    float out1[4] = {};   // d 8..15
    float l0 = 0.f, l1 = 0.f;
    const uint32_t* ksu = (const uint32_t*)Ks;
    const uint32_t* vsu = (const uint32_t*)Vs;
    const int koff = gr * KSTR + ct;
    const int voff = ct * VSTR + gr;
    const int sidx = (lane & ~3) | (ct >> 1);
    const bool odd = (ct & 1);

    for (int t0 = 0; t0 < NN; t0 += 128) {
        __syncthreads();
        {   // stage K (L2-normalized, tf32) and V (tf32) tiles: 128 rows x 16
            const float4* kg = (const float4*)(g_k + base + t0*16);
            const float4* vg = (const float4*)(g_v + base + t0*16);
            #pragma unroll
            for (int t = 0; t < 2; t++) {
                int i4 = tid + t * 256;
                int r = i4 >> 2, cc4 = (i4 & 3) * 4;
                float4 kv = kg[i4];
                float s = kv.x*kv.x + kv.y*kv.y + kv.z*kv.z + kv.w*kv.w;
                s += __shfl_xor_sync(0xffffffffu, s, 1);
                s += __shfl_xor_sync(0xffffffffu, s, 2);
                float inv = 1.0f / fmaxf(sqrtf(s), 1e-12f);
                kv.x = tf32_round(kv.x * inv); kv.y = tf32_round(kv.y * inv);
                kv.z = tf32_round(kv.z * inv); kv.w = tf32_round(kv.w * inv);
                *(float4*)&Ks[r*KSTR + cc4] = kv;
                float4 vv = vg[i4];
                vv.x = tf32_round(vv.x); vv.y = tf32_round(vv.y);
                vv.z = tf32_round(vv.z); vv.w = tf32_round(vv.w);
                *(float4*)&Vs[r*VSTR + cc4] = vv;
            }
        }
        __syncthreads();
        #pragma unroll 8
        for (int kb = 0; kb < 16; kb++) {
            float s[4] = {};
            {
                int ka = kb*8*KSTR + koff;
                mma_tf32(s, qa[0], ksu[ka],   ksu[ka+4]);
                mma_tf32(s, qa[1], ksu[ka+8], ksu[ka+12]);
            }
            float p0 = exp2f(s[0]), p1 = exp2f(s[1]);
            float p2 = exp2f(s[2]), p3 = exp2f(s[3]);
            l0 += p0 + p1;
            l1 += p2 + p3;
            float v00 = __shfl_sync(0xffffffffu, p0, sidx);
            float v01 = __shfl_sync(0xffffffffu, p1, sidx);
            float v02 = __shfl_sync(0xffffffffu, p0, sidx + 2);
            float v03 = __shfl_sync(0xffffffffu, p1, sidx + 2);
            float v10 = __shfl_sync(0xffffffffu, p2, sidx);
            float v11 = __shfl_sync(0xffffffffu, p3, sidx);
            float v12 = __shfl_sync(0xffffffffu, p2, sidx + 2);
            float v13 = __shfl_sync(0xffffffffu, p3, sidx + 2);
            uint32_t pa[4];
            pa[0] = f2tf32(odd ? v01 : v00);
            pa[2] = f2tf32(odd ? v03 : v02);
            pa[1] = f2tf32(odd ? v11 : v10);
            pa[3] = f2tf32(odd ? v13 : v12);
            {
                int va = kb*8*VSTR + voff;
                mma_tf32(out0, pa, vsu[va],   vsu[va + 4*VSTR]);
                mma_tf32(out1, pa, vsu[va+8], vsu[va + 4*VSTR + 8]);
            }
        }
    }
    l0 += __shfl_xor_sync(0xffffffffu, l0, 1);
    l0 += __shfl_xor_sync(0xffffffffu, l0, 2);
    l1 += __shfl_xor_sync(0xffffffffu, l1, 1);
    l1 += __shfl_xor_sync(0xffffffffu, l1, 2);
    const float inv0 = 1.0f / l0;
    const float inv1 = 1.0f / l1;

    const int bh16 = (b*HEADS + h) * 16;
    {
        int d0 = 2*ct;
        g_ao[(size_t)(bh16 + d0    )*NN + qw + gr    ] = out0[0] * inv0;
        g_ao[(size_t)(bh16 + d0 + 1)*NN + qw + gr    ] = out0[1] * inv0;
        g_ao[(size_t)(bh16 + d0    )*NN + qw + gr + 8] = out0[2] * inv1;
        g_ao[(size_t)(bh16 + d0 + 1)*NN + qw + gr + 8] = out0[3] * inv1;
        g_ao[(size_t)(bh16 + 8 + d0    )*NN + qw + gr    ] = out1[0] * inv0;
        g_ao[(size_t)(bh16 + 8 + d0 + 1)*NN + qw + gr    ] = out1[1] * inv0;
        g_ao[(size_t)(bh16 + 8 + d0    )*NN + qw + gr + 8] = out1[2] * inv1;
        g_ao[(size_t)(bh16 + 8 + d0 + 1)*NN + qw + gr + 8] = out1[3] * inv1;
    }
}

// ---------------------------------------------------------------------------
// K5: training-mode BatchNorm2d, in place. One block per channel. float4 I/O.
// ---------------------------------------------------------------------------
__global__ void __launch_bounds__(256) bn_kernel(float* __restrict__ out,
                                                 const float* __restrict__ gamma,
                                                 const float* __restrict__ beta) {
    const int c   = blockIdx.x;
    const int tid = threadIdx.x;
    float s = 0.f, s2 = 0.f;
    #pragma unroll
    for (int b = 0; b < BB; b++) {
        const float4* p = (const float4*)(out + ((size_t)b * CC + c) * NN);
        for (int i = tid; i < NN/4; i += 256) {
            float4 v = p[i];
            s  += v.x + v.y + v.z + v.w;
            s2 = fmaf(v.x, v.x, s2); s2 = fmaf(v.y, v.y, s2);
            s2 = fmaf(v.z, v.z, s2); s2 = fmaf(v.w, v.w, s2);
        }
    }
    __shared__ float rs[256], rs2[256];
    rs[tid] = s; rs2[tid] = s2;
    __syncthreads();
    for (int off = 128; off > 0; off >>= 1) {
        if (tid < off) { rs[tid] += rs[tid+off]; rs2[tid] += rs2[tid+off]; }
        __syncthreads();
    }
    const float invN  = 1.0f / (BB * NN);
    const float mean  = rs[0] * invN;
    float var         = fmaxf(rs2[0] * invN - mean * mean, 0.f);
    const float scale = rsqrtf(var + 1e-5f) * gamma[c];
    const float shift = beta[c] - mean * scale;
    #pragma unroll
    for (int b = 0; b < BB; b++) {
        float4* p = (float4*)(out + ((size_t)b * CC + c) * NN);
        for (int i = tid; i < NN/4; i += 256) {
            float4 v = p[i];
            v.x = fmaf(v.x, scale, shift); v.y = fmaf(v.y, scale, shift);
            v.z = fmaf(v.z, scale, shift); v.w = fmaf(v.w, scale, shift);
            p[i] = v;
        }
    }
}

// ---------------------------------------------------------------------------
extern "C" void kernel_launch(void* const* d_in, const int* in_sizes, int n_in,
                              void* d_out, int out_size) {
    const float* x      = (const float*)d_in[0];
    const float* w_qkv  = (const float*)d_in[1];
    const float* temper = (const float*)d_in[2];
    const float* w_out  = (const float*)d_in[3];
    const float* gamma  = (const float*)d_in[4];
    const float* beta   = (const float*)d_in[5];
    float* out = (float*)d_out;

    qkv_mma <<<dim3(NN/64, M_QKV/64, BB), 256>>>(x, w_qkv);
    attn_mma<<<dim3(NN/128, HEADS, BB), 256>>>(temper);
    proj_mma<<<dim3(NN/64, M_PRJ/64, BB), 256>>>(w_out, out);
    bn_kernel<<<CC, 256>>>(out, gamma, beta);
}

// round 9
// speedup vs baseline: 4.2587x; 1.0922x over previous
#include <cuda_runtime.h>
#include <cuda_bf16.h>
#include <math.h>
#include <stdint.h>

// Problem constants
#define BB     2
#define CC     512
#define HEADS  8
#define DPH    16
#define TOT    128          // HEADS*DPH
#define NN     2304         // 48*48
#define M_QKV  384          // 3*TOT
#define K_QKV  512
#define M_PRJ  512
#define K_PRJ  128

// Scratch (device globals — no allocation allowed)
__device__ float g_q [BB*HEADS*NN*DPH];   // [b][h][n][d]  (UNNORMALIZED)
__device__ float g_k [BB*HEADS*NN*DPH];
__device__ float g_v [BB*HEADS*NN*DPH];
__device__ float g_ao[BB*TOT*NN];         // [b][t][n], t = h*16+d
__device__ float g_bnpart[4*CC*2];        // [slice][c][{sum,sumsq}]
__device__ float g_bnscale[CC];
__device__ float g_bnshift[CC];

__device__ __forceinline__ uint32_t f2tf32(float f) {
    uint32_t u;
    asm("cvt.rna.tf32.f32 %0, %1;" : "=r"(u) : "f"(f));
    return u;
}
__device__ __forceinline__ float tf32_round(float f) {
    return __uint_as_float(f2tf32(f));
}
__device__ __forceinline__ void mma_tf32(float* c,
                                         const uint32_t* a,
                                         uint32_t b0, uint32_t b1) {
    asm volatile("mma.sync.aligned.m16n8k8.row.col.f32.tf32.tf32.f32 "
                 "{%0,%1,%2,%3}, {%4,%5,%6,%7}, {%8,%9}, {%0,%1,%2,%3};"
                 : "+f"(c[0]), "+f"(c[1]), "+f"(c[2]), "+f"(c[3])
                 : "r"(a[0]), "r"(a[1]), "r"(a[2]), "r"(a[3]), "r"(b0), "r"(b1));
}
__device__ __forceinline__ void mma_bf16(float* c,
                                         const uint32_t* a,
                                         uint32_t b0, uint32_t b1) {
    asm volatile("mma.sync.aligned.m16n8k16.row.col.f32.bf16.bf16.f32 "
                 "{%0,%1,%2,%3}, {%4,%5,%6,%7}, {%8,%9}, {%0,%1,%2,%3};"
                 : "+f"(c[0]), "+f"(c[1]), "+f"(c[2]), "+f"(c[3])
                 : "r"(a[0]), "r"(a[1]), "r"(a[2]), "r"(a[3]), "r"(b0), "r"(b1));
}
// pack two floats as bf16x2: low half = lo_elem (smaller k), high half = hi_elem
__device__ __forceinline__ uint32_t pack2bf(float lo_elem, float hi_elem) {
    uint32_t r;
    asm("cvt.rn.bf16x2.f32 %0, %1, %2;" : "=r"(r) : "f"(hi_elem), "f"(lo_elem));
    return r;
}
// residual (lo part) of a 2-term bf16 split, given hi packed word + originals
__device__ __forceinline__ uint32_t split_lo2(uint32_t hpk, float e0, float e1) {
    float h0 = __uint_as_float(hpk << 16);
    float h1 = __uint_as_float(hpk & 0xFFFF0000u);
    return pack2bf(e0 - h0, e1 - h1);
}
__device__ __forceinline__ void ldsm_x2_trans(uint32_t& r0, uint32_t& r1, uint32_t saddr) {
    asm volatile("ldmatrix.sync.aligned.m8n8.x2.trans.shared.b16 {%0,%1}, [%2];"
                 : "=r"(r0), "=r"(r1) : "r"(saddr));
}

// ===========================================================================
// Split-bf16 GEMM (C = A[M,K] @ B[K,N]) — unchanged from R7 (proven).
// ===========================================================================
#define AWS 20     // A row stride in 32-bit words (= 40 bf16)
#define BSTRB 72   // B row stride in bf16 elems

template <int KDIM, typename Epi>
__device__ __forceinline__ void gemm_body(const float* __restrict__ A,
                                          const float* __restrict__ B,
                                          Epi epi) {
    __shared__ __align__(16) uint32_t Ah[64*AWS], Al[64*AWS];
    __shared__ __align__(16) __nv_bfloat16 Bh[32*BSTRB], Bl[32*BSTRB];
    const int tid  = threadIdx.x;
    const int lane = tid & 31;
    const int wid  = tid >> 5;
    const int gr   = lane >> 2;
    const int ct   = lane & 3;
    const int wm   = (wid & 1) * 32;
    const int wn   = (wid >> 1) * 16;
    const int mBase = blockIdx.y * 64;
    const int nBase = blockIdx.x * 64;

    int am[2], ak[2], bk[2], bn[2];
    #pragma unroll
    for (int t = 0; t < 2; t++) {
        int i4 = tid + t * 256;
        am[t] = i4 >> 3;  ak[t] = (i4 & 7) << 2;
        bk[t] = i4 >> 4;  bn[t] = (i4 & 15) << 2;
    }
    float4 areg[2], breg[2];
    #pragma unroll
    for (int t = 0; t < 2; t++) {
        areg[t] = *(const float4*)&A[(mBase + am[t]) * KDIM + ak[t]];
        breg[t] = *(const float4*)&B[(size_t)bk[t] * NN + nBase + bn[t]];
    }
    const int lrow = lane & 15;

    float c[2][2][4] = {};
    for (int ch = 0; ch < KDIM/32; ch++) {
        __syncthreads();
        #pragma unroll
        for (int t = 0; t < 2; t++) {
            uint32_t ah0 = pack2bf(areg[t].x, areg[t].y);
            uint32_t ah1 = pack2bf(areg[t].z, areg[t].w);
            uint32_t al0 = split_lo2(ah0, areg[t].x, areg[t].y);
            uint32_t al1 = split_lo2(ah1, areg[t].z, areg[t].w);
            int awi = am[t]*AWS + (ak[t] >> 1);
            *(uint2*)&Ah[awi] = make_uint2(ah0, ah1);
            *(uint2*)&Al[awi] = make_uint2(al0, al1);
            uint32_t bh0 = pack2bf(breg[t].x, breg[t].y);
            uint32_t bh1 = pack2bf(breg[t].z, breg[t].w);
            uint32_t bl0 = split_lo2(bh0, breg[t].x, breg[t].y);
            uint32_t bl1 = split_lo2(bh1, breg[t].z, breg[t].w);
            int bwi = (bk[t]*BSTRB + bn[t]) >> 1;
            *(uint2*)&((uint32_t*)Bh)[bwi] = make_uint2(bh0, bh1);
            *(uint2*)&((uint32_t*)Bl)[bwi] = make_uint2(bl0, bl1);
        }
        __syncthreads();
        if (ch + 1 < KDIM/32) {
            #pragma unroll
            for (int t = 0; t < 2; t++) {
                areg[t] = *(const float4*)&A[(mBase + am[t]) * KDIM + (ch+1)*32 + ak[t]];
                breg[t] = *(const float4*)&B[(size_t)((ch+1)*32 + bk[t]) * NN + nBase + bn[t]];
            }
        }
        #pragma unroll
        for (int s = 0; s < 2; s++) {
            const int kwo = s * 8;
            const int kro = s * 16;
            uint32_t ah[2][4], al2[2][4];
            #pragma unroll
            for (int mt = 0; mt < 2; mt++) {
                int m0 = wm + mt*16;
                int w00 = (m0+gr  )*AWS + kwo + ct;
                int w10 = (m0+gr+8)*AWS + kwo + ct;
                ah[mt][0]  = Ah[w00];     ah[mt][1]  = Ah[w10];
                ah[mt][2]  = Ah[w00 + 4]; ah[mt][3]  = Ah[w10 + 4];
                al2[mt][0] = Al[w00];     al2[mt][1] = Al[w10];
                al2[mt][2] = Al[w00 + 4]; al2[mt][3] = Al[w10 + 4];
            }
            uint32_t bhf[2][2], blf[2][2];
            #pragma unroll
            for (int nt = 0; nt < 2; nt++) {
                int n0 = wn + nt*8;
                uint32_t ah_addr = (uint32_t)__cvta_generic_to_shared(
                    &Bh[(kro + lrow)*BSTRB + n0]);
                uint32_t al_addr = (uint32_t)__cvta_generic_to_shared(
                    &Bl[(kro + lrow)*BSTRB + n0]);
                ldsm_x2_trans(bhf[nt][0], bhf[nt][1], ah_addr);
                ldsm_x2_trans(blf[nt][0], blf[nt][1], al_addr);
            }
            #pragma unroll
            for (int mt = 0; mt < 2; mt++)
            #pragma unroll
            for (int nt = 0; nt < 2; nt++) {
                mma_bf16(c[mt][nt], ah[mt],  bhf[nt][0], bhf[nt][1]);
                mma_bf16(c[mt][nt], ah[mt],  blf[nt][0], blf[nt][1]);
                mma_bf16(c[mt][nt], al2[mt], bhf[nt][0], bhf[nt][1]);
            }
        }
    }
    #pragma unroll
    for (int mt = 0; mt < 2; mt++)
    #pragma unroll
    for (int nt = 0; nt < 2; nt++)
    #pragma unroll
    for (int e = 0; e < 4; e++) {
        int m = mBase + wm + mt*16 + gr + ((e >= 2) ? 8 : 0);
        int n = nBase + wn + nt*8 + 2*ct + (e & 1);
        epi(m, n, c[mt][nt][e]);
    }
}

// K1: qkv = w_qkv[384,512] @ x[b,512,2304]; scatter into q/k/v [b,h,n,d]
__global__ void __launch_bounds__(256) qkv_mma(const float* __restrict__ x,
                                               const float* __restrict__ w) {
    const int b = blockIdx.z;
    const float* xb = x + (size_t)b * CC * NN;
    gemm_body<K_QKV>(w, xb, [b](int m, int n, float val) {
        int part = m >> 7;
        int t2 = m & 127, h = t2 >> 4, d = t2 & 15;
        int idx = ((b*HEADS + h)*NN + n)*DPH + d;
        if      (part == 0) g_q[idx] = val;
        else if (part == 1) g_k[idx] = val;
        else                g_v[idx] = val;
    });
}

// K4: out[b,c,n] = w_out[512,128] @ ao[b,128,2304]  (raw; BN applied after)
__global__ void __launch_bounds__(256) proj_mma(const float* __restrict__ w,
                                                float* __restrict__ out) {
    const int b = blockIdx.z;
    const float* ao = g_ao + (size_t)b * TOT * NN;
    gemm_body<K_PRJ>(w, ao, [b, out](int m, int n, float val) {
        out[((size_t)b * CC + m) * NN + n] = val;
    });
}

// ===========================================================================
// K3: attention. S = Q.K^T via tf32 m16n8k8 (accuracy-critical).
// PV via SPLIT bf16 m16n8k16: Ph*Vh + Ph*Vl + Pl*Vh (3-term, ~fp32-grade;
// plain bf16 PV fails: out is itself an average, so per-element rounding
// does NOT average out). The S C-fragment maps directly onto the bf16
// A-fragment, so no shuffle relayout. V staged as hi/lo bf16 pair-packed
// along k, dim stride 68 words (banks 4*gr+ct: conflict-free).
// ===========================================================================
#define KSTR 20
#define VWS  68    // V words per dim (64 used + 4 pad)
__global__ void __launch_bounds__(256) attn_mma(const float* __restrict__ temperature) {
    __shared__ float Ks[128*KSTR];
    __shared__ __align__(4) uint32_t Vwh[16*VWS];   // [d][k/2] bf16x2 hi
    __shared__ __align__(4) uint32_t Vwl[16*VWS];   // [d][k/2] bf16x2 lo
    const int b    = blockIdx.z;
    const int h    = blockIdx.y;
    const int tid  = threadIdx.x;
    const int wid  = tid >> 5;
    const int lane = tid & 31;
    const int gr   = lane >> 2;
    const int ct   = lane & 3;
    const float scale = __ldg(&temperature[h]) * 1.4426950408889634f;
    const int base = (b*HEADS + h) * NN * DPH;
    const int qw   = blockIdx.x * 128 + wid * 16;

    // Q fragments with fused L2-norm (tf32, temp*log2e folded)
    uint32_t qa[2][4];
    {
        const float* q0 = g_q + base + (qw+gr  )*DPH;
        const float* q1 = g_q + base + (qw+gr+8)*DPH;
        float r0[4], r1[4];
        #pragma unroll
        for (int j = 0; j < 4; j++) { r0[j] = q0[ct + 4*j]; r1[j] = q1[ct + 4*j]; }
        float s0 = r0[0]*r0[0] + r0[1]*r0[1] + r0[2]*r0[2] + r0[3]*r0[3];
        float s1 = r1[0]*r1[0] + r1[1]*r1[1] + r1[2]*r1[2] + r1[3]*r1[3];
        s0 += __shfl_xor_sync(0xffffffffu, s0, 1);
        s0 += __shfl_xor_sync(0xffffffffu, s0, 2);
        s1 += __shfl_xor_sync(0xffffffffu, s1, 1);
        s1 += __shfl_xor_sync(0xffffffffu, s1, 2);
        float i0 = scale / fmaxf(sqrtf(s0), 1e-12f);
        float i1 = scale / fmaxf(sqrtf(s1), 1e-12f);
        qa[0][0] = f2tf32(r0[0]*i0); qa[0][1] = f2tf32(r1[0]*i1);
        qa[0][2] = f2tf32(r0[1]*i0); qa[0][3] = f2tf32(r1[1]*i1);
        qa[1][0] = f2tf32(r0[2]*i0); qa[1][1] = f2tf32(r1[2]*i1);
        qa[1][2] = f2tf32(r0[3]*i0); qa[1][3] = f2tf32(r1[3]*i1);
    }

    float out0[4] = {};   // d 0..7
    float out1[4] = {};   // d 8..15
    float l0 = 0.f, l1 = 0.f;
    const uint32_t* ksu = (const uint32_t*)Ks;
    const int koff = gr * KSTR + ct;

    for (int t0 = 0; t0 < NN; t0 += 128) {
        __syncthreads();
        {   // stage K (L2-normalized tf32) and V (hi/lo bf16 packed along k)
            const float4* kg = (const float4*)(g_k + base + t0*16);
            const float4* vg = (const float4*)(g_v + base + t0*16);
            __nv_bfloat16* vbh = (__nv_bfloat16*)Vwh;
            __nv_bfloat16* vbl = (__nv_bfloat16*)Vwl;
            #pragma unroll
            for (int t = 0; t < 2; t++) {
                int i4 = tid + t * 256;
                int r = i4 >> 2, cc4 = (i4 & 3) * 4;
                float4 kv = kg[i4];
                float s = kv.x*kv.x + kv.y*kv.y + kv.z*kv.z + kv.w*kv.w;
                s += __shfl_xor_sync(0xffffffffu, s, 1);
                s += __shfl_xor_sync(0xffffffffu, s, 2);
                float inv = 1.0f / fmaxf(sqrtf(s), 1e-12f);
                kv.x = tf32_round(kv.x * inv); kv.y = tf32_round(kv.y * inv);
                kv.z = tf32_round(kv.z * inv); kv.w = tf32_round(kv.w * inv);
                *(float4*)&Ks[r*KSTR + cc4] = kv;
                float4 vv = vg[i4];
                int half = r & 1, k2 = r >> 1;
                float ve[4] = {vv.x, vv.y, vv.z, vv.w};
                #pragma unroll
                for (int d4 = 0; d4 < 4; d4++) {
                    __nv_bfloat16 hi = __float2bfloat16(ve[d4]);
                    int si = ((cc4 + d4)*VWS + k2)*2 + half;
                    vbh[si] = hi;
                    vbl[si] = __float2bfloat16(ve[d4] - __bfloat162float(hi));
                }
            }
        }
        __syncthreads();
        #pragma unroll 4
        for (int kb16 = 0; kb16 < 8; kb16++) {       // 16 keys per iteration
            // S block a: keys kb16*16 .. +7
            float sa[4] = {};
            {
                int ka = (kb16*16)*KSTR + koff;
                mma_tf32(sa, qa[0], ksu[ka],   ksu[ka+4]);
                mma_tf32(sa, qa[1], ksu[ka+8], ksu[ka+12]);
            }
            // S block b: keys kb16*16+8 .. +15
            float sb[4] = {};
            {
                int ka = (kb16*16 + 8)*KSTR + koff;
                mma_tf32(sb, qa[0], ksu[ka],   ksu[ka+4]);
                mma_tf32(sb, qa[1], ksu[ka+8], ksu[ka+12]);
            }
            float pa0 = exp2f(sa[0]), pa1 = exp2f(sa[1]);
            float pa2 = exp2f(sa[2]), pa3 = exp2f(sa[3]);
            float pb0 = exp2f(sb[0]), pb1 = exp2f(sb[1]);
            float pb2 = exp2f(sb[2]), pb3 = exp2f(sb[3]);
            l0 += (pa0 + pa1) + (pb0 + pb1);
            l1 += (pa2 + pa3) + (pb2 + pb3);
            // S C-frag == m16n8k16 A-frag (consecutive-key pairs): hi/lo split
            uint32_t pH[4], pL[4];
            pH[0] = pack2bf(pa0, pa1);  pL[0] = split_lo2(pH[0], pa0, pa1);
            pH[1] = pack2bf(pa2, pa3);  pL[1] = split_lo2(pH[1], pa2, pa3);
            pH[2] = pack2bf(pb0, pb1);  pL[2] = split_lo2(pH[2], pb0, pb1);
            pH[3] = pack2bf(pb2, pb3);  pL[3] = split_lo2(pH[3], pb2, pb3);
            // PV: out += P[16x16] . V[16k x 16d]; 3-term split per n-half
            {
                int kbase = kb16*8 + ct;
                uint32_t vh00 = Vwh[gr*VWS + kbase],     vh01 = Vwh[gr*VWS + kbase + 4];
                uint32_t vl00 = Vwl[gr*VWS + kbase],     vl01 = Vwl[gr*VWS + kbase + 4];
                uint32_t vh10 = Vwh[(8+gr)*VWS + kbase], vh11 = Vwh[(8+gr)*VWS + kbase + 4];
                uint32_t vl10 = Vwl[(8+gr)*VWS + kbase], vl11 = Vwl[(8+gr)*VWS + kbase + 4];
                mma_bf16(out0, pH, vh00, vh01);
                mma_bf16(out0, pH, vl00, vl01);
                mma_bf16(out0, pL, vh00, vh01);
                mma_bf16(out1, pH, vh10, vh11);
                mma_bf16(out1, pH, vl10, vl11);
                mma_bf16(out1, pL, vh10, vh11);
            }
        }
    }
    l0 += __shfl_xor_sync(0xffffffffu, l0, 1);
    l0 += __shfl_xor_sync(0xffffffffu, l0, 2);
    l1 += __shfl_xor_sync(0xffffffffu, l1, 1);
    l1 += __shfl_xor_sync(0xffffffffu, l1, 2);
    const float inv0 = 1.0f / l0;
    const float inv1 = 1.0f / l1;

    const int bh16 = (b*HEADS + h) * 16;
    {
        int d0 = 2*ct;
        g_ao[(size_t)(bh16 + d0    )*NN + qw + gr    ] = out0[0] * inv0;
        g_ao[(size_t)(bh16 + d0 + 1)*NN + qw + gr    ] = out0[1] * inv0;
        g_ao[(size_t)(bh16 + d0    )*NN + qw + gr + 8] = out0[2] * inv1;
        g_ao[(size_t)(bh16 + d0 + 1)*NN + qw + gr + 8] = out0[3] * inv1;
        g_ao[(size_t)(bh16 + 8 + d0    )*NN + qw + gr    ] = out1[0] * inv0;
        g_ao[(size_t)(bh16 + 8 + d0 + 1)*NN + qw + gr    ] = out1[1] * inv0;
        g_ao[(size_t)(bh16 + 8 + d0    )*NN + qw + gr + 8] = out1[2] * inv1;
        g_ao[(size_t)(bh16 + 8 + d0 + 1)*NN + qw + gr + 8] = out1[3] * inv1;
    }
}

// ---------------------------------------------------------------------------
// K5a: BN stats partials. grid (CC, 4), 128 threads.
// ---------------------------------------------------------------------------
__global__ void __launch_bounds__(128) bn_stats(const float* __restrict__ out) {
    const int c   = blockIdx.x;
    const int sl  = blockIdx.y;
    const int tid = threadIdx.x;
    float s = 0.f, s2 = 0.f;
    for (int i = tid; i < 288; i += 128) {
        int fi = sl * 288 + i;
        int b  = fi / 576;
        int n4 = fi % 576;
        float4 v = *(const float4*)(out + ((size_t)b * CC + c) * NN + n4 * 4);
        s  += (v.x + v.y) + (v.z + v.w);
        s2 = fmaf(v.x, v.x, s2); s2 = fmaf(v.y, v.y, s2);
        s2 = fmaf(v.z, v.z, s2); s2 = fmaf(v.w, v.w, s2);
    }
    #pragma unroll
    for (int off = 16; off > 0; off >>= 1) {
        s  += __shfl_xor_sync(0xffffffffu, s, off);
        s2 += __shfl_xor_sync(0xffffffffu, s2, off);
    }
    __shared__ float rs[4], rs2[4];
    if ((tid & 31) == 0) { rs[tid>>5] = s; rs2[tid>>5] = s2; }
    __syncthreads();
    if (tid == 0) {
        g_bnpart[(sl*CC + c)*2 + 0] = rs[0]+rs[1]+rs[2]+rs[3];
        g_bnpart[(sl*CC + c)*2 + 1] = rs2[0]+rs2[1]+rs2[2]+rs2[3];
    }
}

// K5b: finalize scale/shift per channel. grid 2 x 256.
__global__ void __launch_bounds__(256) bn_finalize(const float* __restrict__ gamma,
                                                   const float* __restrict__ beta) {
    int c = blockIdx.x * 256 + threadIdx.x;
    if (c >= CC) return;
    float s = 0.f, s2 = 0.f;
    #pragma unroll
    for (int sl = 0; sl < 4; sl++) {
        s  += g_bnpart[(sl*CC + c)*2 + 0];
        s2 += g_bnpart[(sl*CC + c)*2 + 1];
    }
    const float invN = 1.0f / (BB * NN);
    float mean = s * invN;
    float var  = fmaxf(s2 * invN - mean * mean, 0.f);
    float sc   = rsqrtf(var + 1e-5f) * gamma[c];
    g_bnscale[c] = sc;
    g_bnshift[c] = beta[c] - mean * sc;
}

// K5c: apply. grid = BB*CC*NN/4/256 = 2304 blocks.
__global__ void __launch_bounds__(256) bn_apply(float* __restrict__ out) {
    int fi = blockIdx.x * 256 + threadIdx.x;
    int c  = ((fi * 4) / NN) % CC;
    float sc = g_bnscale[c], sh = g_bnshift[c];
    float4* p = (float4*)out + fi;
    float4 v = *p;
    v.x = fmaf(v.x, sc, sh); v.y = fmaf(v.y, sc, sh);
    v.z = fmaf(v.z, sc, sh); v.w = fmaf(v.w, sc, sh);
    *p = v;
}

// ---------------------------------------------------------------------------
extern "C" void kernel_launch(void* const* d_in, const int* in_sizes, int n_in,
                              void* d_out, int out_size) {
    const float* x      = (const float*)d_in[0];
    const float* w_qkv  = (const float*)d_in[1];
    const float* temper = (const float*)d_in[2];
    const float* w_out  = (const float*)d_in[3];
    const float* gamma  = (const float*)d_in[4];
    const float* beta   = (const float*)d_in[5];
    float* out = (float*)d_out;

    qkv_mma <<<dim3(NN/64, M_QKV/64, BB), 256>>>(x, w_qkv);
    attn_mma<<<dim3(NN/128, HEADS, BB), 256>>>(temper);
    proj_mma<<<dim3(NN/64, M_PRJ/64, BB), 256>>>(w_out, out);
    bn_stats<<<dim3(CC, 4), 128>>>(out);
    bn_finalize<<<2, 256>>>(gamma, beta);
    bn_apply<<<(BB*CC*NN/4)/256, 256>>>(out);
}

// round 10
// speedup vs baseline: 4.3153x; 1.0133x over previous
#include <cuda_runtime.h>
#include <cuda_bf16.h>
#include <cuda_fp16.h>
#include <math.h>
#include <stdint.h>

// Problem constants
#define BB     2
#define CC     512
#define HEADS  8
#define DPH    16
#define TOT    128          // HEADS*DPH
#define NN     2304         // 48*48
#define M_QKV  384          // 3*TOT
#define K_QKV  512
#define M_PRJ  512
#define K_PRJ  128

// Scratch (device globals — no allocation allowed)
__device__ float g_q [BB*HEADS*NN*DPH];   // [b][h][n][d]  (UNNORMALIZED)
__device__ float g_k [BB*HEADS*NN*DPH];
__device__ float g_v [BB*HEADS*NN*DPH];
__device__ float g_ao[BB*TOT*NN];         // [b][t][n], t = h*16+d
__device__ float g_bnpart[4*CC*2];        // [slice][c][{sum,sumsq}]
__device__ float g_bnscale[CC];
__device__ float g_bnshift[CC];

__device__ __forceinline__ uint32_t f2tf32(float f) {
    uint32_t u;
    asm("cvt.rna.tf32.f32 %0, %1;" : "=r"(u) : "f"(f));
    return u;
}
__device__ __forceinline__ float tf32_round(float f) {
    return __uint_as_float(f2tf32(f));
}
__device__ __forceinline__ void mma_tf32(float* c,
                                         const uint32_t* a,
                                         uint32_t b0, uint32_t b1) {
    asm volatile("mma.sync.aligned.m16n8k8.row.col.f32.tf32.tf32.f32 "
                 "{%0,%1,%2,%3}, {%4,%5,%6,%7}, {%8,%9}, {%0,%1,%2,%3};"
                 : "+f"(c[0]), "+f"(c[1]), "+f"(c[2]), "+f"(c[3])
                 : "r"(a[0]), "r"(a[1]), "r"(a[2]), "r"(a[3]), "r"(b0), "r"(b1));
}
__device__ __forceinline__ void mma_bf16(float* c,
                                         const uint32_t* a,
                                         uint32_t b0, uint32_t b1) {
    asm volatile("mma.sync.aligned.m16n8k16.row.col.f32.bf16.bf16.f32 "
                 "{%0,%1,%2,%3}, {%4,%5,%6,%7}, {%8,%9}, {%0,%1,%2,%3};"
                 : "+f"(c[0]), "+f"(c[1]), "+f"(c[2]), "+f"(c[3])
                 : "r"(a[0]), "r"(a[1]), "r"(a[2]), "r"(a[3]), "r"(b0), "r"(b1));
}
__device__ __forceinline__ void mma_f16(float* c,
                                        const uint32_t* a,
                                        uint32_t b0, uint32_t b1) {
    asm volatile("mma.sync.aligned.m16n8k16.row.col.f32.f16.f16.f32 "
                 "{%0,%1,%2,%3}, {%4,%5,%6,%7}, {%8,%9}, {%0,%1,%2,%3};"
                 : "+f"(c[0]), "+f"(c[1]), "+f"(c[2]), "+f"(c[3])
                 : "r"(a[0]), "r"(a[1]), "r"(a[2]), "r"(a[3]), "r"(b0), "r"(b1));
}
// pack two floats as bf16x2 / f16x2: low half = lo_elem, high half = hi_elem
__device__ __forceinline__ uint32_t pack2bf(float lo_elem, float hi_elem) {
    uint32_t r;
    asm("cvt.rn.bf16x2.f32 %0, %1, %2;" : "=r"(r) : "f"(hi_elem), "f"(lo_elem));
    return r;
}
__device__ __forceinline__ uint32_t pack2h(float lo_elem, float hi_elem) {
    uint32_t r;
    asm("cvt.rn.f16x2.f32 %0, %1, %2;" : "=r"(r) : "f"(hi_elem), "f"(lo_elem));
    return r;
}
// residual (lo part) of a 2-term bf16 split
__device__ __forceinline__ uint32_t split_lo2(uint32_t hpk, float e0, float e1) {
    float h0 = __uint_as_float(hpk << 16);
    float h1 = __uint_as_float(hpk & 0xFFFF0000u);
    return pack2bf(e0 - h0, e1 - h1);
}
__device__ __forceinline__ void ldsm_x2_trans(uint32_t& r0, uint32_t& r1, uint32_t saddr) {
    asm volatile("ldmatrix.sync.aligned.m8n8.x2.trans.shared.b16 {%0,%1}, [%2];"
                 : "=r"(r0), "=r"(r1) : "r"(saddr));
}

// ===========================================================================
// Split-bf16 GEMM (C = A[M,K] @ B[K,N]), DOUBLE-BUFFERED smem: one sync per
// chunk, staging overlapped with MMA work. 3-MMA hi/lo split (fp32-grade).
// ===========================================================================
#define AWS 20     // A row stride in 32-bit words (= 40 bf16)
#define BSTRB 72   // B row stride in bf16 elems

template <int KDIM, typename Epi>
__device__ __forceinline__ void gemm_body(const float* __restrict__ A,
                                          const float* __restrict__ B,
                                          Epi epi) {
    __shared__ __align__(16) uint32_t Ah[2][64*AWS], Al[2][64*AWS];
    __shared__ __align__(16) __nv_bfloat16 Bh[2][32*BSTRB], Bl[2][32*BSTRB];
    const int tid  = threadIdx.x;
    const int lane = tid & 31;
    const int wid  = tid >> 5;
    const int gr   = lane >> 2;
    const int ct   = lane & 3;
    const int wm   = (wid & 1) * 32;
    const int wn   = (wid >> 1) * 16;
    const int mBase = blockIdx.y * 64;
    const int nBase = blockIdx.x * 64;
    const int lrow = lane & 15;

    int am[2], ak[2], bk[2], bn[2];
    #pragma unroll
    for (int t = 0; t < 2; t++) {
        int i4 = tid + t * 256;
        am[t] = i4 >> 3;  ak[t] = (i4 & 7) << 2;
        bk[t] = i4 >> 4;  bn[t] = (i4 & 15) << 2;
    }
    float4 areg[2], breg[2];
    #pragma unroll
    for (int t = 0; t < 2; t++) {
        areg[t] = *(const float4*)&A[(mBase + am[t]) * KDIM + ak[t]];
        breg[t] = *(const float4*)&B[(size_t)bk[t] * NN + nBase + bn[t]];
    }
    // stage chunk 0 into buffer 0
    #pragma unroll
    for (int t = 0; t < 2; t++) {
        uint32_t ah0 = pack2bf(areg[t].x, areg[t].y);
        uint32_t ah1 = pack2bf(areg[t].z, areg[t].w);
        uint32_t al0 = split_lo2(ah0, areg[t].x, areg[t].y);
        uint32_t al1 = split_lo2(ah1, areg[t].z, areg[t].w);
        int awi = am[t]*AWS + (ak[t] >> 1);
        *(uint2*)&Ah[0][awi] = make_uint2(ah0, ah1);
        *(uint2*)&Al[0][awi] = make_uint2(al0, al1);
        uint32_t bh0 = pack2bf(breg[t].x, breg[t].y);
        uint32_t bh1 = pack2bf(breg[t].z, breg[t].w);
        uint32_t bl0 = split_lo2(bh0, breg[t].x, breg[t].y);
        uint32_t bl1 = split_lo2(bh1, breg[t].z, breg[t].w);
        int bwi = (bk[t]*BSTRB + bn[t]) >> 1;
        *(uint2*)&((uint32_t*)Bh[0])[bwi] = make_uint2(bh0, bh1);
        *(uint2*)&((uint32_t*)Bl[0])[bwi] = make_uint2(bl0, bl1);
    }
    __syncthreads();

    float c[2][2][4] = {};
    #pragma unroll 2
    for (int ch = 0; ch < KDIM/32; ch++) {
        const int cur = ch & 1;
        const bool more = (ch + 1 < KDIM/32);
        if (more) {                        // prefetch next chunk (LDG behind MMAs)
            #pragma unroll
            for (int t = 0; t < 2; t++) {
                areg[t] = *(const float4*)&A[(mBase + am[t]) * KDIM + (ch+1)*32 + ak[t]];
                breg[t] = *(const float4*)&B[(size_t)((ch+1)*32 + bk[t]) * NN + nBase + bn[t]];
            }
        }
        #pragma unroll
        for (int s = 0; s < 2; s++) {
            const int kwo = s * 8;
            const int kro = s * 16;
            uint32_t ah[2][4], al2[2][4];
            #pragma unroll
            for (int mt = 0; mt < 2; mt++) {
                int m0 = wm + mt*16;
                int w00 = (m0+gr  )*AWS + kwo + ct;
                int w10 = (m0+gr+8)*AWS + kwo + ct;
                ah[mt][0]  = Ah[cur][w00];     ah[mt][1]  = Ah[cur][w10];
                ah[mt][2]  = Ah[cur][w00 + 4]; ah[mt][3]  = Ah[cur][w10 + 4];
                al2[mt][0] = Al[cur][w00];     al2[mt][1] = Al[cur][w10];
                al2[mt][2] = Al[cur][w00 + 4]; al2[mt][3] = Al[cur][w10 + 4];
            }
            uint32_t bhf[2][2], blf[2][2];
            #pragma unroll
            for (int nt = 0; nt < 2; nt++) {
                int n0 = wn + nt*8;
                uint32_t hadr = (uint32_t)__cvta_generic_to_shared(
                    &Bh[cur][(kro + lrow)*BSTRB + n0]);
                uint32_t ladr = (uint32_t)__cvta_generic_to_shared(
                    &Bl[cur][(kro + lrow)*BSTRB + n0]);
                ldsm_x2_trans(bhf[nt][0], bhf[nt][1], hadr);
                ldsm_x2_trans(blf[nt][0], blf[nt][1], ladr);
            }
            #pragma unroll
            for (int mt = 0; mt < 2; mt++)
            #pragma unroll
            for (int nt = 0; nt < 2; nt++) {
                mma_bf16(c[mt][nt], ah[mt],  bhf[nt][0], bhf[nt][1]);
                mma_bf16(c[mt][nt], ah[mt],  blf[nt][0], blf[nt][1]);
                mma_bf16(c[mt][nt], al2[mt], bhf[nt][0], bhf[nt][1]);
            }
        }
        if (more) {                        // stage next chunk into other buffer
            const int nxt = cur ^ 1;
            #pragma unroll
            for (int t = 0; t < 2; t++) {
                uint32_t ah0 = pack2bf(areg[t].x, areg[t].y);
                uint32_t ah1 = pack2bf(areg[t].z, areg[t].w);
                uint32_t al0 = split_lo2(ah0, areg[t].x, areg[t].y);
                uint32_t al1 = split_lo2(ah1, areg[t].z, areg[t].w);
                int awi = am[t]*AWS + (ak[t] >> 1);
                *(uint2*)&Ah[nxt][awi] = make_uint2(ah0, ah1);
                *(uint2*)&Al[nxt][awi] = make_uint2(al0, al1);
                uint32_t bh0 = pack2bf(breg[t].x, breg[t].y);
                uint32_t bh1 = pack2bf(breg[t].z, breg[t].w);
                uint32_t bl0 = split_lo2(bh0, breg[t].x, breg[t].y);
                uint32_t bl1 = split_lo2(bh1, breg[t].z, breg[t].w);
                int bwi = (bk[t]*BSTRB + bn[t]) >> 1;
                *(uint2*)&((uint32_t*)Bh[nxt])[bwi] = make_uint2(bh0, bh1);
                *(uint2*)&((uint32_t*)Bl[nxt])[bwi] = make_uint2(bl0, bl1);
            }
        }
        __syncthreads();
    }
    #pragma unroll
    for (int mt = 0; mt < 2; mt++)
    #pragma unroll
    for (int nt = 0; nt < 2; nt++)
    #pragma unroll
    for (int e = 0; e < 4; e++) {
        int m = mBase + wm + mt*16 + gr + ((e >= 2) ? 8 : 0);
        int n = nBase + wn + nt*8 + 2*ct + (e & 1);
        epi(m, n, c[mt][nt][e]);
    }
}

// K1: qkv = w_qkv[384,512] @ x[b,512,2304]; scatter into q/k/v [b,h,n,d]
__global__ void __launch_bounds__(256) qkv_mma(const float* __restrict__ x,
                                               const float* __restrict__ w) {
    const int b = blockIdx.z;
    const float* xb = x + (size_t)b * CC * NN;
    gemm_body<K_QKV>(w, xb, [b](int m, int n, float val) {
        int part = m >> 7;
        int t2 = m & 127, h = t2 >> 4, d = t2 & 15;
        int idx = ((b*HEADS + h)*NN + n)*DPH + d;
        if      (part == 0) g_q[idx] = val;
        else if (part == 1) g_k[idx] = val;
        else                g_v[idx] = val;
    });
}

// K4: out[b,c,n] = w_out[512,128] @ ao[b,128,2304]  (raw; BN applied after)
__global__ void __launch_bounds__(256) proj_mma(const float* __restrict__ w,
                                                float* __restrict__ out) {
    const int b = blockIdx.z;
    const float* ao = g_ao + (size_t)b * TOT * NN;
    gemm_body<K_PRJ>(w, ao, [b, out](int m, int n, float val) {
        out[((size_t)b * CC + m) * NN + n] = val;
    });
}

// ===========================================================================
// K3: attention. S = Q.K^T via tf32 m16n8k8 (accuracy-critical).
// PV via single fp16 m16n8k16 (f16 = bf16_err/8; calibrated from R8's
// measured 2.7e-3 with bf16 => ~3.4e-4 here, under threshold with margin).
// S C-fragment maps directly onto the f16 A-fragment: no shuffle relayout.
// V staged f16 pair-packed along k, dim stride 68 words (conflict-free).
// ===========================================================================
#define KSTR 20
#define VWS  68    // V words per dim (64 used + 4 pad)
__global__ void __launch_bounds__(256) attn_mma(const float* __restrict__ temperature) {
    __shared__ float Ks[128*KSTR];
    __shared__ __align__(4) uint32_t Vw[16*VWS];   // [d][k/2] f16x2
    const int b    = blockIdx.z;
    const int h    = blockIdx.y;
    const int tid  = threadIdx.x;
    const int wid  = tid >> 5;
    const int lane = tid & 31;
    const int gr   = lane >> 2;
    const int ct   = lane & 3;
    const float scale = __ldg(&temperature[h]) * 1.4426950408889634f;
    const int base = (b*HEADS + h) * NN * DPH;
    const int qw   = blockIdx.x * 128 + wid * 16;

    // Q fragments with fused L2-norm (tf32, temp*log2e folded)
    uint32_t qa[2][4];
    {
        const float* q0 = g_q + base + (qw+gr  )*DPH;
        const float* q1 = g_q + base + (qw+gr+8)*DPH;
        float r0[4], r1[4];
        #pragma unroll
        for (int j = 0; j < 4; j++) { r0[j] = q0[ct + 4*j]; r1[j] = q1[ct + 4*j]; }
        float s0 = r0[0]*r0[0] + r0[1]*r0[1] + r0[2]*r0[2] + r0[3]*r0[3];
        float s1 = r1[0]*r1[0] + r1[1]*r1[1] + r1[2]*r1[2] + r1[3]*r1[3];
        s0 += __shfl_xor_sync(0xffffffffu, s0, 1);
        s0 += __shfl_xor_sync(0xffffffffu, s0, 2);
        s1 += __shfl_xor_sync(0xffffffffu, s1, 1);
        s1 += __shfl_xor_sync(0xffffffffu, s1, 2);
        float i0 = scale / fmaxf(sqrtf(s0), 1e-12f);
        float i1 = scale / fmaxf(sqrtf(s1), 1e-12f);
        qa[0][0] = f2tf32(r0[0]*i0); qa[0][1] = f2tf32(r1[0]*i1);
        qa[0][2] = f2tf32(r0[1]*i0); qa[0][3] = f2tf32(r1[1]*i1);
        qa[1][0] = f2tf32(r0[2]*i0); qa[1][1] = f2tf32(r1[2]*i1);
        qa[1][2] = f2tf32(r0[3]*i0); qa[1][3] = f2tf32(r1[3]*i1);
    }

    float out0[4] = {};   // d 0..7
    float out1[4] = {};   // d 8..15
    float l0 = 0.f, l1 = 0.f;
    const uint32_t* ksu = (const uint32_t*)Ks;
    const int koff = gr * KSTR + ct;

    for (int t0 = 0; t0 < NN; t0 += 128) {
        __syncthreads();
        {   // stage K (L2-normalized tf32) and V (f16 packed along k)
            const float4* kg = (const float4*)(g_k + base + t0*16);
            const float4* vg = (const float4*)(g_v + base + t0*16);
            __half* vb = (__half*)Vw;
            #pragma unroll
            for (int t = 0; t < 2; t++) {
                int i4 = tid + t * 256;
                int r = i4 >> 2, cc4 = (i4 & 3) * 4;
                float4 kv = kg[i4];
                float s = kv.x*kv.x + kv.y*kv.y + kv.z*kv.z + kv.w*kv.w;
                s += __shfl_xor_sync(0xffffffffu, s, 1);
                s += __shfl_xor_sync(0xffffffffu, s, 2);
                float inv = 1.0f / fmaxf(sqrtf(s), 1e-12f);
                kv.x = tf32_round(kv.x * inv); kv.y = tf32_round(kv.y * inv);
                kv.z = tf32_round(kv.z * inv); kv.w = tf32_round(kv.w * inv);
                *(float4*)&Ks[r*KSTR + cc4] = kv;
                float4 vv = vg[i4];
                int half_i = r & 1, k2 = r >> 1;
                vb[((cc4+0)*VWS + k2)*2 + half_i] = __float2half_rn(vv.x);
                vb[((cc4+1)*VWS + k2)*2 + half_i] = __float2half_rn(vv.y);
                vb[((cc4+2)*VWS + k2)*2 + half_i] = __float2half_rn(vv.z);
                vb[((cc4+3)*VWS + k2)*2 + half_i] = __float2half_rn(vv.w);
            }
        }
        __syncthreads();
        #pragma unroll 4
        for (int kb16 = 0; kb16 < 8; kb16++) {       // 16 keys per iteration
            float sa[4] = {};
            {
                int ka = (kb16*16)*KSTR + koff;
                mma_tf32(sa, qa[0], ksu[ka],   ksu[ka+4]);
                mma_tf32(sa, qa[1], ksu[ka+8], ksu[ka+12]);
            }
            float sb[4] = {};
            {
                int ka = (kb16*16 + 8)*KSTR + koff;
                mma_tf32(sb, qa[0], ksu[ka],   ksu[ka+4]);
                mma_tf32(sb, qa[1], ksu[ka+8], ksu[ka+12]);
            }
            float pa0 = exp2f(sa[0]), pa1 = exp2f(sa[1]);
            float pa2 = exp2f(sa[2]), pa3 = exp2f(sa[3]);
            float pb0 = exp2f(sb[0]), pb1 = exp2f(sb[1]);
            float pb2 = exp2f(sb[2]), pb3 = exp2f(sb[3]);
            l0 += (pa0 + pa1) + (pb0 + pb1);
            l1 += (pa2 + pa3) + (pb2 + pb3);
            // S C-frag == m16n8k16 A-frag: direct f16 pack, no relayout
            uint32_t pH[4];
            pH[0] = pack2h(pa0, pa1);
            pH[1] = pack2h(pa2, pa3);
            pH[2] = pack2h(pb0, pb1);
            pH[3] = pack2h(pb2, pb3);
            {
                int kbase = kb16*8 + ct;
                mma_f16(out0, pH, Vw[gr*VWS + kbase],     Vw[gr*VWS + kbase + 4]);
                mma_f16(out1, pH, Vw[(8+gr)*VWS + kbase], Vw[(8+gr)*VWS + kbase + 4]);
            }
        }
    }
    l0 += __shfl_xor_sync(0xffffffffu, l0, 1);
    l0 += __shfl_xor_sync(0xffffffffu, l0, 2);
    l1 += __shfl_xor_sync(0xffffffffu, l1, 1);
    l1 += __shfl_xor_sync(0xffffffffu, l1, 2);
    const float inv0 = 1.0f / l0;
    const float inv1 = 1.0f / l1;

    const int bh16 = (b*HEADS + h) * 16;
    {
        int d0 = 2*ct;
        g_ao[(size_t)(bh16 + d0    )*NN + qw + gr    ] = out0[0] * inv0;
        g_ao[(size_t)(bh16 + d0 + 1)*NN + qw + gr    ] = out0[1] * inv0;
        g_ao[(size_t)(bh16 + d0    )*NN + qw + gr + 8] = out0[2] * inv1;
        g_ao[(size_t)(bh16 + d0 + 1)*NN + qw + gr + 8] = out0[3] * inv1;
        g_ao[(size_t)(bh16 + 8 + d0    )*NN + qw + gr    ] = out1[0] * inv0;
        g_ao[(size_t)(bh16 + 8 + d0 + 1)*NN + qw + gr    ] = out1[1] * inv0;
        g_ao[(size_t)(bh16 + 8 + d0    )*NN + qw + gr + 8] = out1[2] * inv1;
        g_ao[(size_t)(bh16 + 8 + d0 + 1)*NN + qw + gr + 8] = out1[3] * inv1;
    }
}

// ---------------------------------------------------------------------------
// K5a: BN stats partials. grid (CC, 4), 128 threads.
// ---------------------------------------------------------------------------
__global__ void __launch_bounds__(128) bn_stats(const float* __restrict__ out) {
    const int c   = blockIdx.x;
    const int sl  = blockIdx.y;
    const int tid = threadIdx.x;
    float s = 0.f, s2 = 0.f;
    for (int i = tid; i < 288; i += 128) {
        int fi = sl * 288 + i;
        int b  = fi / 576;
        int n4 = fi % 576;
        float4 v = *(const float4*)(out + ((size_t)b * CC + c) * NN + n4 * 4);
        s  += (v.x + v.y) + (v.z + v.w);
        s2 = fmaf(v.x, v.x, s2); s2 = fmaf(v.y, v.y, s2);
        s2 = fmaf(v.z, v.z, s2); s2 = fmaf(v.w, v.w, s2);
    }
    #pragma unroll
    for (int off = 16; off > 0; off >>= 1) {
        s  += __shfl_xor_sync(0xffffffffu, s, off);
        s2 += __shfl_xor_sync(0xffffffffu, s2, off);
    }
    __shared__ float rs[4], rs2[4];
    if ((tid & 31) == 0) { rs[tid>>5] = s; rs2[tid>>5] = s2; }
    __syncthreads();
    if (tid == 0) {
        g_bnpart[(sl*CC + c)*2 + 0] = rs[0]+rs[1]+rs[2]+rs[3];
        g_bnpart[(sl*CC + c)*2 + 1] = rs2[0]+rs2[1]+rs2[2]+rs2[3];
    }
}

// K5b: finalize scale/shift per channel. grid 2 x 256.
__global__ void __launch_bounds__(256) bn_finalize(const float* __restrict__ gamma,
                                                   const float* __restrict__ beta) {
    int c = blockIdx.x * 256 + threadIdx.x;
    if (c >= CC) return;
    float s = 0.f, s2 = 0.f;
    #pragma unroll
    for (int sl = 0; sl < 4; sl++) {
        s  += g_bnpart[(sl*CC + c)*2 + 0];
        s2 += g_bnpart[(sl*CC + c)*2 + 1];
    }
    const float invN = 1.0f / (BB * NN);
    float mean = s * invN;
    float var  = fmaxf(s2 * invN - mean * mean, 0.f);
    float sc   = rsqrtf(var + 1e-5f) * gamma[c];
    g_bnscale[c] = sc;
    g_bnshift[c] = beta[c] - mean * sc;
}

// K5c: apply. grid = BB*CC*NN/4/256 = 2304 blocks.
__global__ void __launch_bounds__(256) bn_apply(float* __restrict__ out) {
    int fi = blockIdx.x * 256 + threadIdx.x;
    int c  = ((fi * 4) / NN) % CC;
    float sc = g_bnscale[c], sh = g_bnshift[c];
    float4* p = (float4*)out + fi;
    float4 v = *p;
    v.x = fmaf(v.x, sc, sh); v.y = fmaf(v.y, sc, sh);
    v.z = fmaf(v.z, sc, sh); v.w = fmaf(v.w, sc, sh);
    *p = v;
}

// ---------------------------------------------------------------------------
extern "C" void kernel_launch(void* const* d_in, const int* in_sizes, int n_in,
                              void* d_out, int out_size) {
    const float* x      = (const float*)d_in[0];
    const float* w_qkv  = (const float*)d_in[1];
    const float* temper = (const float*)d_in[2];
    const float* w_out  = (const float*)d_in[3];
    const float* gamma  = (const float*)d_in[4];
    const float* beta   = (const float*)d_in[5];
    float* out = (float*)d_out;

    qkv_mma <<<dim3(NN/64, M_QKV/64, BB), 256>>>(x, w_qkv);
    attn_mma<<<dim3(NN/128, HEADS, BB), 256>>>(temper);
    proj_mma<<<dim3(NN/64, M_PRJ/64, BB), 256>>>(w_out, out);
    bn_stats<<<dim3(CC, 4), 128>>>(out);
    bn_finalize<<<2, 256>>>(gamma, beta);
    bn_apply<<<(BB*CC*NN/4)/256, 256>>>(out);
}

// round 11
// speedup vs baseline: 5.5244x; 1.2802x over previous
#include <cuda_runtime.h>
#include <cuda_bf16.h>
#include <cuda_fp16.h>
#include <math.h>
#include <stdint.h>

// Problem constants
#define BB     2
#define CC     512
#define HEADS  8
#define DPH    16
#define TOT    128          // HEADS*DPH
#define NN     2304         // 48*48
#define M_QKV  384          // 3*TOT
#define K_QKV  512
#define M_PRJ  512
#define K_PRJ  128
#define NSPLIT 2
#define CHUNK  (NN / NSPLIT)   // 1152

// Scratch (device globals — no allocation allowed)
__device__ float g_q [BB*HEADS*NN*DPH];   // [b][h][n][d]  (UNNORMALIZED)
__device__ float g_k [BB*HEADS*NN*DPH];
__device__ float g_v [BB*HEADS*NN*DPH];
__device__ float g_ao[BB*TOT*NN];         // [b][t][n], t = h*16+d
__device__ float g_part[NSPLIT*BB*HEADS*DPH*NN];  // [s][bh][d][n]
__device__ float g_lsum[NSPLIT*BB*HEADS*NN];      // [s][bh][n]
__device__ float g_bnpart[4*CC*2];        // [slice][c][{sum,sumsq}]
__device__ float g_bnscale[CC];
__device__ float g_bnshift[CC];

__device__ __forceinline__ uint32_t f2tf32(float f) {
    uint32_t u;
    asm("cvt.rna.tf32.f32 %0, %1;" : "=r"(u) : "f"(f));
    return u;
}
__device__ __forceinline__ float tf32_round(float f) {
    return __uint_as_float(f2tf32(f));
}
__device__ __forceinline__ float ex2f(float x) {   // single MUFU.EX2, guaranteed
    float r;
    asm("ex2.approx.ftz.f32 %0, %1;" : "=f"(r) : "f"(x));
    return r;
}
__device__ __forceinline__ void mma_tf32(float* c,
                                         const uint32_t* a,
                                         uint32_t b0, uint32_t b1) {
    asm volatile("mma.sync.aligned.m16n8k8.row.col.f32.tf32.tf32.f32 "
                 "{%0,%1,%2,%3}, {%4,%5,%6,%7}, {%8,%9}, {%0,%1,%2,%3};"
                 : "+f"(c[0]), "+f"(c[1]), "+f"(c[2]), "+f"(c[3])
                 : "r"(a[0]), "r"(a[1]), "r"(a[2]), "r"(a[3]), "r"(b0), "r"(b1));
}
__device__ __forceinline__ void mma_bf16(float* c,
                                         const uint32_t* a,
                                         uint32_t b0, uint32_t b1) {
    asm volatile("mma.sync.aligned.m16n8k16.row.col.f32.bf16.bf16.f32 "
                 "{%0,%1,%2,%3}, {%4,%5,%6,%7}, {%8,%9}, {%0,%1,%2,%3};"
                 : "+f"(c[0]), "+f"(c[1]), "+f"(c[2]), "+f"(c[3])
                 : "r"(a[0]), "r"(a[1]), "r"(a[2]), "r"(a[3]), "r"(b0), "r"(b1));
}
__device__ __forceinline__ void mma_f16(float* c,
                                        const uint32_t* a,
                                        uint32_t b0, uint32_t b1) {
    asm volatile("mma.sync.aligned.m16n8k16.row.col.f32.f16.f16.f32 "
                 "{%0,%1,%2,%3}, {%4,%5,%6,%7}, {%8,%9}, {%0,%1,%2,%3};"
                 : "+f"(c[0]), "+f"(c[1]), "+f"(c[2]), "+f"(c[3])
                 : "r"(a[0]), "r"(a[1]), "r"(a[2]), "r"(a[3]), "r"(b0), "r"(b1));
}
__device__ __forceinline__ uint32_t pack2bf(float lo_elem, float hi_elem) {
    uint32_t r;
    asm("cvt.rn.bf16x2.f32 %0, %1, %2;" : "=r"(r) : "f"(hi_elem), "f"(lo_elem));
    return r;
}
__device__ __forceinline__ uint32_t pack2h(float lo_elem, float hi_elem) {
    uint32_t r;
    asm("cvt.rn.f16x2.f32 %0, %1, %2;" : "=r"(r) : "f"(hi_elem), "f"(lo_elem));
    return r;
}
__device__ __forceinline__ uint32_t split_lo2(uint32_t hpk, float e0, float e1) {
    float h0 = __uint_as_float(hpk << 16);
    float h1 = __uint_as_float(hpk & 0xFFFF0000u);
    return pack2bf(e0 - h0, e1 - h1);
}
__device__ __forceinline__ void ldsm_x2_trans(uint32_t& r0, uint32_t& r1, uint32_t saddr) {
    asm volatile("ldmatrix.sync.aligned.m8n8.x2.trans.shared.b16 {%0,%1}, [%2];"
                 : "=r"(r0), "=r"(r1) : "r"(saddr));
}

// ===========================================================================
// Split-bf16 GEMM, double-buffered (unchanged from R10 — passing at best).
// ===========================================================================
#define AWS 20
#define BSTRB 72

template <int KDIM, typename Epi>
__device__ __forceinline__ void gemm_body(const float* __restrict__ A,
                                          const float* __restrict__ B,
                                          Epi epi) {
    __shared__ __align__(16) uint32_t Ah[2][64*AWS], Al[2][64*AWS];
    __shared__ __align__(16) __nv_bfloat16 Bh[2][32*BSTRB], Bl[2][32*BSTRB];
    const int tid  = threadIdx.x;
    const int lane = tid & 31;
    const int wid  = tid >> 5;
    const int gr   = lane >> 2;
    const int ct   = lane & 3;
    const int wm   = (wid & 1) * 32;
    const int wn   = (wid >> 1) * 16;
    const int mBase = blockIdx.y * 64;
    const int nBase = blockIdx.x * 64;
    const int lrow = lane & 15;

    int am[2], ak[2], bk[2], bn[2];
    #pragma unroll
    for (int t = 0; t < 2; t++) {
        int i4 = tid + t * 256;
        am[t] = i4 >> 3;  ak[t] = (i4 & 7) << 2;
        bk[t] = i4 >> 4;  bn[t] = (i4 & 15) << 2;
    }
    float4 areg[2], breg[2];
    #pragma unroll
    for (int t = 0; t < 2; t++) {
        areg[t] = *(const float4*)&A[(mBase + am[t]) * KDIM + ak[t]];
        breg[t] = *(const float4*)&B[(size_t)bk[t] * NN + nBase + bn[t]];
    }
    #pragma unroll
    for (int t = 0; t < 2; t++) {
        uint32_t ah0 = pack2bf(areg[t].x, areg[t].y);
        uint32_t ah1 = pack2bf(areg[t].z, areg[t].w);
        uint32_t al0 = split_lo2(ah0, areg[t].x, areg[t].y);
        uint32_t al1 = split_lo2(ah1, areg[t].z, areg[t].w);
        int awi = am[t]*AWS + (ak[t] >> 1);
        *(uint2*)&Ah[0][awi] = make_uint2(ah0, ah1);
        *(uint2*)&Al[0][awi] = make_uint2(al0, al1);
        uint32_t bh0 = pack2bf(breg[t].x, breg[t].y);
        uint32_t bh1 = pack2bf(breg[t].z, breg[t].w);
        uint32_t bl0 = split_lo2(bh0, breg[t].x, breg[t].y);
        uint32_t bl1 = split_lo2(bh1, breg[t].z, breg[t].w);
        int bwi = (bk[t]*BSTRB + bn[t]) >> 1;
        *(uint2*)&((uint32_t*)Bh[0])[bwi] = make_uint2(bh0, bh1);
        *(uint2*)&((uint32_t*)Bl[0])[bwi] = make_uint2(bl0, bl1);
    }
    __syncthreads();

    float c[2][2][4] = {};
    #pragma unroll 2
    for (int ch = 0; ch < KDIM/32; ch++) {
        const int cur = ch & 1;
        const bool more = (ch + 1 < KDIM/32);
        if (more) {
            #pragma unroll
            for (int t = 0; t < 2; t++) {
                areg[t] = *(const float4*)&A[(mBase + am[t]) * KDIM + (ch+1)*32 + ak[t]];
                breg[t] = *(const float4*)&B[(size_t)((ch+1)*32 + bk[t]) * NN + nBase + bn[t]];
            }
        }
        #pragma unroll
        for (int s = 0; s < 2; s++) {
            const int kwo = s * 8;
            const int kro = s * 16;
            uint32_t ah[2][4], al2[2][4];
            #pragma unroll
            for (int mt = 0; mt < 2; mt++) {
                int m0 = wm + mt*16;
                int w00 = (m0+gr  )*AWS + kwo + ct;
                int w10 = (m0+gr+8)*AWS + kwo + ct;
                ah[mt][0]  = Ah[cur][w00];     ah[mt][1]  = Ah[cur][w10];
                ah[mt][2]  = Ah[cur][w00 + 4]; ah[mt][3]  = Ah[cur][w10 + 4];
                al2[mt][0] = Al[cur][w00];     al2[mt][1] = Al[cur][w10];
                al2[mt][2] = Al[cur][w00 + 4]; al2[mt][3] = Al[cur][w10 + 4];
            }
            uint32_t bhf[2][2], blf[2][2];
            #pragma unroll
            for (int nt = 0; nt < 2; nt++) {
                int n0 = wn + nt*8;
                uint32_t hadr = (uint32_t)__cvta_generic_to_shared(
                    &Bh[cur][(kro + lrow)*BSTRB + n0]);
                uint32_t ladr = (uint32_t)__cvta_generic_to_shared(
                    &Bl[cur][(kro + lrow)*BSTRB + n0]);
                ldsm_x2_trans(bhf[nt][0], bhf[nt][1], hadr);
                ldsm_x2_trans(blf[nt][0], blf[nt][1], ladr);
            }
            #pragma unroll
            for (int mt = 0; mt < 2; mt++)
            #pragma unroll
            for (int nt = 0; nt < 2; nt++) {
                mma_bf16(c[mt][nt], ah[mt],  bhf[nt][0], bhf[nt][1]);
                mma_bf16(c[mt][nt], ah[mt],  blf[nt][0], blf[nt][1]);
                mma_bf16(c[mt][nt], al2[mt], bhf[nt][0], bhf[nt][1]);
            }
        }
        if (more) {
            const int nxt = cur ^ 1;
            #pragma unroll
            for (int t = 0; t < 2; t++) {
                uint32_t ah0 = pack2bf(areg[t].x, areg[t].y);
                uint32_t ah1 = pack2bf(areg[t].z, areg[t].w);
                uint32_t al0 = split_lo2(ah0, areg[t].x, areg[t].y);
                uint32_t al1 = split_lo2(ah1, areg[t].z, areg[t].w);
                int awi = am[t]*AWS + (ak[t] >> 1);
                *(uint2*)&Ah[nxt][awi] = make_uint2(ah0, ah1);
                *(uint2*)&Al[nxt][awi] = make_uint2(al0, al1);
                uint32_t bh0 = pack2bf(breg[t].x, breg[t].y);
                uint32_t bh1 = pack2bf(breg[t].z, breg[t].w);
                uint32_t bl0 = split_lo2(bh0, breg[t].x, breg[t].y);
                uint32_t bl1 = split_lo2(bh1, breg[t].z, breg[t].w);
                int bwi = (bk[t]*BSTRB + bn[t]) >> 1;
                *(uint2*)&((uint32_t*)Bh[nxt])[bwi] = make_uint2(bh0, bh1);
                *(uint2*)&((uint32_t*)Bl[nxt])[bwi] = make_uint2(bl0, bl1);
            }
        }
        __syncthreads();
    }
    #pragma unroll
    for (int mt = 0; mt < 2; mt++)
    #pragma unroll
    for (int nt = 0; nt < 2; nt++)
    #pragma unroll
    for (int e = 0; e < 4; e++) {
        int m = mBase + wm + mt*16 + gr + ((e >= 2) ? 8 : 0);
        int n = nBase + wn + nt*8 + 2*ct + (e & 1);
        epi(m, n, c[mt][nt][e]);
    }
}

// K1: qkv = w_qkv[384,512] @ x[b,512,2304]; scatter into q/k/v [b,h,n,d]
__global__ void __launch_bounds__(256) qkv_mma(const float* __restrict__ x,
                                               const float* __restrict__ w) {
    const int b = blockIdx.z;
    const float* xb = x + (size_t)b * CC * NN;
    gemm_body<K_QKV>(w, xb, [b](int m, int n, float val) {
        int part = m >> 7;
        int t2 = m & 127, h = t2 >> 4, d = t2 & 15;
        int idx = ((b*HEADS + h)*NN + n)*DPH + d;
        if      (part == 0) g_q[idx] = val;
        else if (part == 1) g_k[idx] = val;
        else                g_v[idx] = val;
    });
}

// K4: out[b,c,n] = w_out[512,128] @ ao[b,128,2304]
__global__ void __launch_bounds__(256) proj_mma(const float* __restrict__ w,
                                                float* __restrict__ out) {
    const int b = blockIdx.z;
    const float* ao = g_ao + (size_t)b * TOT * NN;
    gemm_body<K_PRJ>(w, ao, [b, out](int m, int n, float val) {
        out[((size_t)b * CC + m) * NN + n] = val;
    });
}

// ===========================================================================
// K3: attention, 2-WAY KEY SPLIT (576 blocks => ~7.8 warps/SMSP for latency
// hiding; kernel was stall-bound at 3.9). S via tf32 m16n8k8; PV via f16
// m16n8k16 with direct C->A fragment mapping. Partials + l written raw;
// combine kernel normalizes. exp = single MUFU.EX2 via asm.
// ===========================================================================
#define KSTR 20
#define VWS  68
__global__ void __launch_bounds__(256) attn_mma(const float* __restrict__ temperature) {
    __shared__ float Ks[128*KSTR];
    __shared__ __align__(4) uint32_t Vw[16*VWS];
    const int b     = blockIdx.z;
    const int h     = blockIdx.y;
    const int split = blockIdx.x / (NN/128);   // 0..1
    const int qblk  = blockIdx.x % (NN/128);   // 0..17
    const int tid  = threadIdx.x;
    const int wid  = tid >> 5;
    const int lane = tid & 31;
    const int gr   = lane >> 2;
    const int ct   = lane & 3;
    const float scale = __ldg(&temperature[h]) * 1.4426950408889634f;
    const int base = (b*HEADS + h) * NN * DPH;
    const int qw   = qblk * 128 + wid * 16;
    const int cstart = split * CHUNK;

    // Q fragments with fused L2-norm (tf32, temp*log2e folded)
    uint32_t qa[2][4];
    {
        const float* q0 = g_q + base + (qw+gr  )*DPH;
        const float* q1 = g_q + base + (qw+gr+8)*DPH;
        float r0[4], r1[4];
        #pragma unroll
        for (int j = 0; j < 4; j++) { r0[j] = q0[ct + 4*j]; r1[j] = q1[ct + 4*j]; }
        float s0 = r0[0]*r0[0] + r0[1]*r0[1] + r0[2]*r0[2] + r0[3]*r0[3];
        float s1 = r1[0]*r1[0] + r1[1]*r1[1] + r1[2]*r1[2] + r1[3]*r1[3];
        s0 += __shfl_xor_sync(0xffffffffu, s0, 1);
        s0 += __shfl_xor_sync(0xffffffffu, s0, 2);
        s1 += __shfl_xor_sync(0xffffffffu, s1, 1);
        s1 += __shfl_xor_sync(0xffffffffu, s1, 2);
        float i0 = scale / fmaxf(sqrtf(s0), 1e-12f);
        float i1 = scale / fmaxf(sqrtf(s1), 1e-12f);
        qa[0][0] = f2tf32(r0[0]*i0); qa[0][1] = f2tf32(r1[0]*i1);
        qa[0][2] = f2tf32(r0[1]*i0); qa[0][3] = f2tf32(r1[1]*i1);
        qa[1][0] = f2tf32(r0[2]*i0); qa[1][1] = f2tf32(r1[2]*i1);
        qa[1][2] = f2tf32(r0[3]*i0); qa[1][3] = f2tf32(r1[3]*i1);
    }

    float out0[4] = {};   // d 0..7
    float out1[4] = {};   // d 8..15
    float l0 = 0.f, l1 = 0.f;
    const uint32_t* ksu = (const uint32_t*)Ks;
    const int koff = gr * KSTR + ct;

    for (int t0 = 0; t0 < CHUNK; t0 += 128) {
        __syncthreads();
        {   // stage K (L2-normalized tf32) and V (f16 packed along k)
            const float4* kg = (const float4*)(g_k + base + (cstart + t0)*16);
            const float4* vg = (const float4*)(g_v + base + (cstart + t0)*16);
            __half* vb = (__half*)Vw;
            #pragma unroll
            for (int t = 0; t < 2; t++) {
                int i4 = tid + t * 256;
                int r = i4 >> 2, cc4 = (i4 & 3) * 4;
                float4 kv = kg[i4];
                float s = kv.x*kv.x + kv.y*kv.y + kv.z*kv.z + kv.w*kv.w;
                s += __shfl_xor_sync(0xffffffffu, s, 1);
                s += __shfl_xor_sync(0xffffffffu, s, 2);
                float inv = 1.0f / fmaxf(sqrtf(s), 1e-12f);
                kv.x = tf32_round(kv.x * inv); kv.y = tf32_round(kv.y * inv);
                kv.z = tf32_round(kv.z * inv); kv.w = tf32_round(kv.w * inv);
                *(float4*)&Ks[r*KSTR + cc4] = kv;
                float4 vv = vg[i4];
                int half_i = r & 1, k2 = r >> 1;
                vb[((cc4+0)*VWS + k2)*2 + half_i] = __float2half_rn(vv.x);
                vb[((cc4+1)*VWS + k2)*2 + half_i] = __float2half_rn(vv.y);
                vb[((cc4+2)*VWS + k2)*2 + half_i] = __float2half_rn(vv.z);
                vb[((cc4+3)*VWS + k2)*2 + half_i] = __float2half_rn(vv.w);
            }
        }
        __syncthreads();
        #pragma unroll 4
        for (int kb16 = 0; kb16 < 8; kb16++) {
            float sa[4] = {};
            {
                int ka = (kb16*16)*KSTR + koff;
                mma_tf32(sa, qa[0], ksu[ka],   ksu[ka+4]);
                mma_tf32(sa, qa[1], ksu[ka+8], ksu[ka+12]);
            }
            float sb[4] = {};
            {
                int ka = (kb16*16 + 8)*KSTR + koff;
                mma_tf32(sb, qa[0], ksu[ka],   ksu[ka+4]);
                mma_tf32(sb, qa[1], ksu[ka+8], ksu[ka+12]);
            }
            float pa0 = ex2f(sa[0]), pa1 = ex2f(sa[1]);
            float pa2 = ex2f(sa[2]), pa3 = ex2f(sa[3]);
            float pb0 = ex2f(sb[0]), pb1 = ex2f(sb[1]);
            float pb2 = ex2f(sb[2]), pb3 = ex2f(sb[3]);
            l0 += (pa0 + pa1) + (pb0 + pb1);
            l1 += (pa2 + pa3) + (pb2 + pb3);
            uint32_t pH[4];
            pH[0] = pack2h(pa0, pa1);
            pH[1] = pack2h(pa2, pa3);
            pH[2] = pack2h(pb0, pb1);
            pH[3] = pack2h(pb2, pb3);
            {
                int kbase = kb16*8 + ct;
                mma_f16(out0, pH, Vw[gr*VWS + kbase],     Vw[gr*VWS + kbase + 4]);
                mma_f16(out1, pH, Vw[(8+gr)*VWS + kbase], Vw[(8+gr)*VWS + kbase + 4]);
            }
        }
    }
    l0 += __shfl_xor_sync(0xffffffffu, l0, 1);
    l0 += __shfl_xor_sync(0xffffffffu, l0, 2);
    l1 += __shfl_xor_sync(0xffffffffu, l1, 1);
    l1 += __shfl_xor_sync(0xffffffffu, l1, 2);

    // write raw partials + denominators: g_part[split][bh][d][n], g_lsum[split][bh][n]
    const int bh = b*HEADS + h;
    float* pp = g_part + ((size_t)(split*BB*HEADS + bh) * DPH) * NN;
    {
        int d0 = 2*ct;
        pp[(size_t)(d0    )*NN + qw + gr    ] = out0[0];
        pp[(size_t)(d0 + 1)*NN + qw + gr    ] = out0[1];
        pp[(size_t)(d0    )*NN + qw + gr + 8] = out0[2];
        pp[(size_t)(d0 + 1)*NN + qw + gr + 8] = out0[3];
        pp[(size_t)(8 + d0    )*NN + qw + gr    ] = out1[0];
        pp[(size_t)(8 + d0 + 1)*NN + qw + gr    ] = out1[1];
        pp[(size_t)(8 + d0    )*NN + qw + gr + 8] = out1[2];
        pp[(size_t)(8 + d0 + 1)*NN + qw + gr + 8] = out1[3];
        float* lp = g_lsum + (size_t)(split*BB*HEADS + bh) * NN;
        lp[qw + gr    ] = l0;    // all 4 quad threads write same value (benign)
        lp[qw + gr + 8] = l1;
    }
}

// K3b: combine 2 split partials, normalize, write g_ao. Fully coalesced.
// threads = NSPLIT-combine over BB*HEADS*DPH*NN/4 float4s = 147456.
__global__ void __launch_bounds__(256) combine_kernel() {
    int idx = blockIdx.x * 256 + threadIdx.x;
    const int NQ4 = NN / 4;
    int n4 = idx % NQ4;
    int r  = idx / NQ4;
    int d  = r & 15;
    int bh = r >> 4;
    const float4 p0 = *(const float4*)&g_part[((size_t)(0*BB*HEADS + bh) * DPH + d) * NN + n4*4];
    const float4 p1 = *(const float4*)&g_part[((size_t)(1*BB*HEADS + bh) * DPH + d) * NN + n4*4];
    const float4 la = *(const float4*)&g_lsum[(size_t)(0*BB*HEADS + bh) * NN + n4*4];
    const float4 lb = *(const float4*)&g_lsum[(size_t)(1*BB*HEADS + bh) * NN + n4*4];
    float4 o;
    o.x = (p0.x + p1.x) / (la.x + lb.x);
    o.y = (p0.y + p1.y) / (la.y + lb.y);
    o.z = (p0.z + p1.z) / (la.z + lb.z);
    o.w = (p0.w + p1.w) / (la.w + lb.w);
    *(float4*)&g_ao[(size_t)(bh*DPH + d) * NN + n4*4] = o;
}

// ---------------------------------------------------------------------------
// K5a/b/c: BatchNorm (unchanged from R10)
// ---------------------------------------------------------------------------
__global__ void __launch_bounds__(128) bn_stats(const float* __restrict__ out) {
    const int c   = blockIdx.x;
    const int sl  = blockIdx.y;
    const int tid = threadIdx.x;
    float s = 0.f, s2 = 0.f;
    for (int i = tid; i < 288; i += 128) {
        int fi = sl * 288 + i;
        int b  = fi / 576;
        int n4 = fi % 576;
        float4 v = *(const float4*)(out + ((size_t)b * CC + c) * NN + n4 * 4);
        s  += (v.x + v.y) + (v.z + v.w);
        s2 = fmaf(v.x, v.x, s2); s2 = fmaf(v.y, v.y, s2);
        s2 = fmaf(v.z, v.z, s2); s2 = fmaf(v.w, v.w, s2);
    }
    #pragma unroll
    for (int off = 16; off > 0; off >>= 1) {
        s  += __shfl_xor_sync(0xffffffffu, s, off);
        s2 += __shfl_xor_sync(0xffffffffu, s2, off);
    }
    __shared__ float rs[4], rs2[4];
    if ((tid & 31) == 0) { rs[tid>>5] = s; rs2[tid>>5] = s2; }
    __syncthreads();
    if (tid == 0) {
        g_bnpart[(sl*CC + c)*2 + 0] = rs[0]+rs[1]+rs[2]+rs[3];
        g_bnpart[(sl*CC + c)*2 + 1] = rs2[0]+rs2[1]+rs2[2]+rs2[3];
    }
}

__global__ void __launch_bounds__(256) bn_finalize(const float* __restrict__ gamma,
                                                   const float* __restrict__ beta) {
    int c = blockIdx.x * 256 + threadIdx.x;
    if (c >= CC) return;
    float s = 0.f, s2 = 0.f;
    #pragma unroll
    for (int sl = 0; sl < 4; sl++) {
        s  += g_bnpart[(sl*CC + c)*2 + 0];
        s2 += g_bnpart[(sl*CC + c)*2 + 1];
    }
    const float invN = 1.0f / (BB * NN);
    float mean = s * invN;
    float var  = fmaxf(s2 * invN - mean * mean, 0.f);
    float sc   = rsqrtf(var + 1e-5f) * gamma[c];
    g_bnscale[c] = sc;
    g_bnshift[c] = beta[c] - mean * sc;
}

__global__ void __launch_bounds__(256) bn_apply(float* __restrict__ out) {
    int fi = blockIdx.x * 256 + threadIdx.x;
    int c  = ((fi * 4) / NN) % CC;
    float sc = g_bnscale[c], sh = g_bnshift[c];
    float4* p = (float4*)out + fi;
    float4 v = *p;
    v.x = fmaf(v.x, sc, sh); v.y = fmaf(v.y, sc, sh);
    v.z = fmaf(v.z, sc, sh); v.w = fmaf(v.w, sc, sh);
    *p = v;
}

// ---------------------------------------------------------------------------
extern "C" void kernel_launch(void* const* d_in, const int* in_sizes, int n_in,
                              void* d_out, int out_size) {
    const float* x      = (const float*)d_in[0];
    const float* w_qkv  = (const float*)d_in[1];
    const float* temper = (const float*)d_in[2];
    const float* w_out  = (const float*)d_in[3];
    const float* gamma  = (const float*)d_in[4];
    const float* beta   = (const float*)d_in[5];
    float* out = (float*)d_out;

    qkv_mma <<<dim3(NN/64, M_QKV/64, BB), 256>>>(x, w_qkv);
    attn_mma<<<dim3((NN/128)*NSPLIT, HEADS, BB), 256>>>(temper);
    combine_kernel<<<(BB*HEADS*DPH*NN/4)/256, 256>>>();
    proj_mma<<<dim3(NN/64, M_PRJ/64, BB), 256>>>(w_out, out);
    bn_stats<<<dim3(CC, 4), 128>>>(out);
    bn_finalize<<<2, 256>>>(gamma, beta);
    bn_apply<<<(BB*CC*NN/4)/256, 256>>>(out);
}